// round 12
// baseline (speedup 1.0000x reference)
#include <cuda_runtime.h>
#include <cuda_fp16.h>
#include <math.h>
#include <stdint.h>

// ---------------- problem-size caps (fixed by setup_inputs) ----------------
#define MAXN 50000
#define NPADMAX 50048   // MAXN rounded up to 128

// ---------------- device scratch (no allocation allowed) -------------------
__device__ int   g_tmp[3 * MAXN];    // deg | cnt | cur (one memset)
__device__ int   g_roff[MAXN + 1];
__device__ int   g_esrc[800000];     // CSR column (src only; weights factorized)
__device__ float g_dis[MAXN];        // deg^-1/2
__device__ float g_xs[MAXN * 3];     // dis*x (layer1 gather source, fp32)
__device__ float g_t1d[MAXN * 3];    // T1 fp32
__device__ float g_t1s[MAXN * 3];    // dis*T1 fp32
__device__ float g_wbias[1344];      // combined gate biases (l1|l2|l3)
__device__ float g_w1t[9 * 768];     // layer1 gate weights transposed fp32
__device__ __align__(256) __half g_xA[(size_t)NPADMAX * 128];  // scaled feats A
__device__ __align__(256) __half g_xB[(size_t)NPADMAX * 128];  // scaled feats B
__device__ __align__(256) __half g_bufA[(size_t)NPADMAX * 384]; // gconv A
__device__ __align__(256) __half g_bufB[(size_t)NPADMAX * 256]; // lin A / gate-out
__device__ __align__(256) __half g_bbuf[262144];                // weights fp16

// weight buffer element offsets (rows x Kp, single fp16)
#define O_B2  24576    // l2 gate: 384 x 384
#define O_B3  172032   // l3 gate: 192 x 192
#define O_BL1 208896   // lin1: 128 x 256
#define O_BL2 241664   // lin2: 64 x 128

// ====================== graph preprocessing ================================

__global__ void k_degree(const int* __restrict__ src, const int* __restrict__ dst, int E) {
    int e = blockIdx.x * blockDim.x + threadIdx.x;
    if (e >= E) return;
    atomicAdd(&g_tmp[src[e]], 1);            // deg (by src, as in reference)
    atomicAdd(&g_tmp[MAXN + dst[e]], 1);     // cnt (CSR row sizes by dst)
}

__global__ void k_scan(int n) {
    __shared__ int ssum[1024];
    int tid = threadIdx.x;
    const int T = 1024;
    int chunk = (n + T - 1) / T;
    int beg = tid * chunk;
    int end = beg + chunk; if (end > n) end = n;
    int s = 0;
    for (int i = beg; i < end; i++) s += g_tmp[MAXN + i];
    ssum[tid] = s;
    __syncthreads();
    for (int off = 1; off < T; off <<= 1) {
        int v = (tid >= off) ? ssum[tid - off] : 0;
        __syncthreads();
        ssum[tid] += v;
        __syncthreads();
    }
    int run = (tid > 0) ? ssum[tid - 1] : 0;
    for (int i = beg; i < end; i++) { g_roff[i] = run; run += g_tmp[MAXN + i]; }
    if (tid == T - 1) g_roff[n] = ssum[T - 1];
    // dis = deg^-1/2 (src-based degree, matching reference)
    for (int i = beg; i < end; i++) {
        int d = g_tmp[i];
        g_dis[i] = d > 0 ? rsqrtf((float)d) : 0.0f;
    }
}

__global__ void k_fill(const int* __restrict__ src, const int* __restrict__ dst, int E) {
    int e = blockIdx.x * blockDim.x + threadIdx.x;
    if (e >= E) return;
    int s = src[e], d = dst[e];
    int pos = g_roff[d] + atomicAdd(&g_tmp[2 * MAXN + d], 1);
    g_esrc[pos] = s;
}

__global__ void k_xs(const float* __restrict__ x, int n) {
    int i = blockIdx.x * blockDim.x + threadIdx.x;
    if (i >= n) return;
    float d = g_dis[i];
    g_xs[i * 3] = d * x[i * 3];
    g_xs[i * 3 + 1] = d * x[i * 3 + 1];
    g_xs[i * 3 + 2] = d * x[i * 3 + 2];
}

// ====================== merged weight/bias preprocessing ===================

__device__ __forceinline__ void prep_gateB(const float* __restrict__ Wx, int F, int H,
                                           int Kp, int nrow, int kk,
                                           __half* __restrict__ dst) {
    int gp = nrow / H, o = nrow % H;
    int gate = (gp == 0) ? 0 : (gp + 1);   // gates {0,2,3}
    float w = 0.0f;
    if (kk < 3 * F) {
        int kc = kk / F, f = kk % F;
        w = Wx[(((size_t)gate * 3 + kc) * F + f) * H + o];
    }
    dst[(size_t)nrow * Kp + kk] = __float2half_rn(w);
}

__device__ __forceinline__ void prep_linB(const float* __restrict__ W, int Hout,
                                          int Kp, int nrow, int kk,
                                          __half* __restrict__ dst) {
    dst[(size_t)nrow * Kp + kk] = __float2half_rn(W[(size_t)kk * Hout + nrow]);
}

#define E1 24576     // 768*32 (layer1 -> transposed fp32 table)
#define E2 172032    // +384*384
#define E3 208896    // +192*192
#define E4 241664    // +128*256
#define E5 249856    // +64*128
#define E6 251200    // +1344 biases

__global__ void k_prep_all(
    const float* __restrict__ w1, const float* __restrict__ w2, const float* __restrict__ w3,
    const float* __restrict__ wl1, const float* __restrict__ wl2,
    const float* __restrict__ bx1, const float* __restrict__ bh1, const float* __restrict__ b1,
    const float* __restrict__ bx2, const float* __restrict__ bh2, const float* __restrict__ b2,
    const float* __restrict__ bx3, const float* __restrict__ bh3, const float* __restrict__ b3) {
    int idx = blockIdx.x * blockDim.x + threadIdx.x;
    if (idx >= E6) return;
    if (idx < E1) {
        int nrow = idx / 32, kk = idx % 32;
        if (kk < 9) {
            int gp = nrow / 256, o = nrow % 256;
            int gate = (gp == 0) ? 0 : (gp + 1);
            int kc = kk / 3, f = kk % 3;
            g_w1t[kk * 768 + nrow] = w1[(((size_t)gate * 3 + kc) * 3 + f) * 256 + o];
        }
    } else if (idx < E2) {
        int t = idx - E1;
        prep_gateB(w2, 128, 128, 384, t / 384, t % 384, g_bbuf + O_B2);
    } else if (idx < E3) {
        int t = idx - E2;
        prep_gateB(w3, 64, 64, 192, t / 192, t % 192, g_bbuf + O_B3);
    } else if (idx < E4) {
        int t = idx - E3;
        prep_linB(wl1, 128, 256, t / 256, t % 256, g_bbuf + O_BL1);
    } else if (idx < E5) {
        int t = idx - E4;
        prep_linB(wl2, 64, 128, t / 128, t % 128, g_bbuf + O_BL2);
    } else {
        int t = idx - E5;
        const float *bx, *bh, *bb; int H, base;
        if (t < 768)       { bx = bx1; bh = bh1; bb = b1; H = 256; base = 0; }
        else if (t < 1152) { bx = bx2; bh = bh2; bb = b2; H = 128; base = 768; t -= 768; }
        else               { bx = bx3; bh = bh3; bb = b3; H = 64;  base = 1152; t -= 1152; }
        int gp = t / H, o = t % H;
        int gate = (gp == 0) ? 0 : (gp + 1);
        g_wbias[base + t] = bx[gate * H + o] + bh[gate * H + o] + bb[gate * H + o];
    }
}

// ====================== fast transcendentals (HW tanh) =====================

__device__ __forceinline__ float ftanh(float x) {
    float y;
    asm("tanh.approx.f32 %0, %1;" : "=f"(y) : "f"(x));
    return y;
}
__device__ __forceinline__ float fsig(float x) {
    return fmaf(ftanh(0.5f * x), 0.5f, 0.5f);
}

// ====================== layer-1: T1 dense pass (unroll-4) ==================
// T1 = -dis[row] * sum(g_xs[src]); also emits dis*T1 for the T2 gather.

__global__ void k_l1a(float* __restrict__ t1d, float* __restrict__ t1s, int n) {
    int row = blockIdx.x * blockDim.x + threadIdx.x;
    if (row >= n) return;
    float t1[3] = {0, 0, 0};
    int j0 = g_roff[row], j1 = g_roff[row + 1];
    int j = j0;
    int jend = j0 + ((j1 - j0) & ~3);
    for (; j < jend; j += 4) {
        int s0 = g_esrc[j], s1 = g_esrc[j + 1], s2 = g_esrc[j + 2], s3 = g_esrc[j + 3];
        const float* x0 = g_xs + (size_t)s0 * 3;
        const float* x1 = g_xs + (size_t)s1 * 3;
        const float* x2 = g_xs + (size_t)s2 * 3;
        const float* x3 = g_xs + (size_t)s3 * 3;
        t1[0] += x0[0] + x1[0] + x2[0] + x3[0];
        t1[1] += x0[1] + x1[1] + x2[1] + x3[1];
        t1[2] += x0[2] + x1[2] + x2[2] + x3[2];
    }
    for (; j < j1; j++) {
        const float* xr = g_xs + (size_t)g_esrc[j] * 3;
        t1[0] += xr[0]; t1[1] += xr[1]; t1[2] += xr[2];
    }
    float dr = g_dis[row];
    float v0 = -dr * t1[0], v1 = -dr * t1[1], v2 = -dr * t1[2];
    t1d[row * 3] = v0; t1d[row * 3 + 1] = v1; t1d[row * 3 + 2] = v2;
    t1s[row * 3] = dr * v0; t1s[row * 3 + 1] = dr * v1; t1s[row * 3 + 2] = dr * v2;
}

// ====================== layer-1 fused: T2 gather + gates -> bufB ===========

__global__ __launch_bounds__(256) void k_l1gates(
    const float* __restrict__ x, const float* __restrict__ t1d,
    const float* __restrict__ t1s,
    const float* __restrict__ wcO, __half* __restrict__ outA, int n, int npad) {
    __shared__ __half sW[9 * 768];
    __shared__ float sB[768];
    int tid = threadIdx.x;
    for (int i = tid; i < 9 * 768; i += 256) sW[i] = __float2half_rn(g_w1t[i]);
    for (int i = tid; i < 768; i += 256) sB[i] = g_wbias[i];
    __syncthreads();
    const __half2* sW2 = reinterpret_cast<const __half2*>(sW);
    int lane = tid & 31, w = tid >> 5;

    for (int rr = 0; rr < 8; rr++) {
        int r = blockIdx.x * 64 + w * 8 + rr;
        if (r >= npad) return;
        if (r >= n) {
#pragma unroll
            for (int c = 0; c < 4; c++)
                *reinterpret_cast<__half2*>(outA + (size_t)r * 256 + 2 * lane + 64 * c) =
                    __floats2half2_rn(0.f, 0.f);
            continue;
        }
        float p0 = 0.f, p1 = 0.f, p2 = 0.f;
        int j0 = g_roff[r], j1 = g_roff[r + 1];
        for (int j = j0 + lane; j < j1; j += 32) {
            const float* tr = t1s + (size_t)g_esrc[j] * 3;
            p0 += tr[0]; p1 += tr[1]; p2 += tr[2];
        }
#pragma unroll
        for (int off = 16; off; off >>= 1) {
            p0 += __shfl_xor_sync(0xffffffffu, p0, off);
            p1 += __shfl_xor_sync(0xffffffffu, p1, off);
            p2 += __shfl_xor_sync(0xffffffffu, p2, off);
        }
        float dr = g_dis[r];
        p0 = -dr * p0; p1 = -dr * p1; p2 = -dr * p2;
        float a[9];
        a[0] = x[r * 3]; a[1] = x[r * 3 + 1]; a[2] = x[r * 3 + 2];
        a[3] = t1d[r * 3]; a[4] = t1d[r * 3 + 1]; a[5] = t1d[r * 3 + 2];
        a[6] = 2.f * p0 - a[0]; a[7] = 2.f * p1 - a[1]; a[8] = 2.f * p2 - a[2];

        float2 pi[4], pc[4], po[4];
#pragma unroll
        for (int c = 0; c < 4; c++) {
            int u = 2 * lane + 64 * c;
            pi[c] = make_float2(sB[u], sB[u + 1]);
            pc[c] = make_float2(sB[256 + u], sB[256 + u + 1]);
            po[c] = make_float2(sB[512 + u], sB[512 + u + 1]);
        }
#pragma unroll
        for (int k = 0; k < 9; k++) {
            float ak = a[k];
            int kb = k * 384;
#pragma unroll
            for (int c = 0; c < 4; c++) {
                int h2i = lane + 32 * c;
                float2 wi = __half22float2(sW2[kb + h2i]);
                pi[c].x += ak * wi.x; pi[c].y += ak * wi.y;
                float2 wc2 = __half22float2(sW2[kb + 128 + h2i]);
                pc[c].x += ak * wc2.x; pc[c].y += ak * wc2.y;
                float2 wo = __half22float2(sW2[kb + 256 + h2i]);
                po[c].x += ak * wo.x; po[c].y += ak * wo.y;
            }
        }
#pragma unroll
        for (int c = 0; c < 4; c++) {
            int u = 2 * lane + 64 * c;
            float I0 = fsig(pi[c].x), T0 = ftanh(pc[c].x), C0 = I0 * T0;
            float O0 = fsig(po[c].x + wcO[u] * C0);
            float y0 = O0 * ftanh(C0); y0 = y0 > 0.f ? y0 : 0.1f * y0;
            float I1 = fsig(pi[c].y), T1 = ftanh(pc[c].y), C1 = I1 * T1;
            float O1 = fsig(po[c].y + wcO[u + 1] * C1);
            float y1 = O1 * ftanh(C1); y1 = y1 > 0.f ? y1 : 0.1f * y1;
            *reinterpret_cast<__half2*>(outA + (size_t)r * 256 + u) =
                __floats2half2_rn(y0, y1);
        }
    }
}

// ====================== SpMV on pre-scaled features ========================
// T = -dis[row] * sum(Xs[src]); CHEB2: T = 2*T - T0 (T0 read from A2 sec0).
// Writes A2 section; optionally the next scaled gather source dis[row]*T.

template <int F, int CHEB2>
__global__ void k_spmv_split(const __half* __restrict__ Xs,
                             const __half* __restrict__ T0buf,
                             __half* __restrict__ XsOut,
                             __half* __restrict__ A2, int Kp, int sec,
                             int n, int npad) {
    const int TPR = F / 4;
    int tid = threadIdx.x;
    int row = blockIdx.x * (256 / TPR) + tid / TPR;
    int f = (tid % TPR) * 4;
    if (row >= npad) return;
    float a0 = 0.f, a1 = 0.f, a2 = 0.f, a3 = 0.f;
    float dr = 0.f;
    if (row < n) {
        int j0 = g_roff[row], j1 = g_roff[row + 1];
        int j = j0;
        int jend = j0 + ((j1 - j0) & ~3);
        for (; j < jend; j += 4) {
            int s0 = g_esrc[j], s1 = g_esrc[j + 1];
            int s2 = g_esrc[j + 2], s3 = g_esrc[j + 3];
            float2 r0 = *reinterpret_cast<const float2*>(Xs + (size_t)s0 * F + f);
            float2 r1 = *reinterpret_cast<const float2*>(Xs + (size_t)s1 * F + f);
            float2 r2 = *reinterpret_cast<const float2*>(Xs + (size_t)s2 * F + f);
            float2 r3 = *reinterpret_cast<const float2*>(Xs + (size_t)s3 * F + f);
            {
                float2 f01 = __half22float2(*reinterpret_cast<__half2*>(&r0.x));
                float2 f23 = __half22float2(*reinterpret_cast<__half2*>(&r0.y));
                a0 += f01.x; a1 += f01.y; a2 += f23.x; a3 += f23.y;
            }
            {
                float2 f01 = __half22float2(*reinterpret_cast<__half2*>(&r1.x));
                float2 f23 = __half22float2(*reinterpret_cast<__half2*>(&r1.y));
                a0 += f01.x; a1 += f01.y; a2 += f23.x; a3 += f23.y;
            }
            {
                float2 f01 = __half22float2(*reinterpret_cast<__half2*>(&r2.x));
                float2 f23 = __half22float2(*reinterpret_cast<__half2*>(&r2.y));
                a0 += f01.x; a1 += f01.y; a2 += f23.x; a3 += f23.y;
            }
            {
                float2 f01 = __half22float2(*reinterpret_cast<__half2*>(&r3.x));
                float2 f23 = __half22float2(*reinterpret_cast<__half2*>(&r3.y));
                a0 += f01.x; a1 += f01.y; a2 += f23.x; a3 += f23.y;
            }
        }
        for (; j < j1; j++) {
            float2 raw = *reinterpret_cast<const float2*>(Xs + (size_t)g_esrc[j] * F + f);
            float2 f01 = __half22float2(*reinterpret_cast<__half2*>(&raw.x));
            float2 f23 = __half22float2(*reinterpret_cast<__half2*>(&raw.y));
            a0 += f01.x; a1 += f01.y; a2 += f23.x; a3 += f23.y;
        }
        dr = g_dis[row];
        a0 = -dr * a0; a1 = -dr * a1; a2 = -dr * a2; a3 = -dr * a3;
        if (CHEB2) {
            float2 raw = *reinterpret_cast<const float2*>(T0buf + (size_t)row * Kp + f);
            float2 f01 = __half22float2(*reinterpret_cast<__half2*>(&raw.x));
            float2 f23 = __half22float2(*reinterpret_cast<__half2*>(&raw.y));
            a0 = 2.f * a0 - f01.x; a1 = 2.f * a1 - f01.y;
            a2 = 2.f * a2 - f23.x; a3 = 2.f * a3 - f23.y;
        }
    }
    float2 packed;
    *reinterpret_cast<__half2*>(&packed.x) = __floats2half2_rn(a0, a1);
    *reinterpret_cast<__half2*>(&packed.y) = __floats2half2_rn(a2, a3);
    *reinterpret_cast<float2*>(A2 + (size_t)row * Kp + sec + f) = packed;
    if (XsOut && row < n) {
        float2 sp;
        *reinterpret_cast<__half2*>(&sp.x) = __floats2half2_rn(dr * a0, dr * a1);
        *reinterpret_cast<__half2*>(&sp.y) = __floats2half2_rn(dr * a2, dr * a3);
        *reinterpret_cast<float2*>(XsOut + (size_t)row * F + f) = sp;
    }
}

// ====================== mma.sync common helpers ============================

#define CP16(dst, src) \
    asm volatile("cp.async.ca.shared.global [%0], [%1], 16;\n" :: "r"(dst), "l"(src))
#define CP_COMMIT() asm volatile("cp.async.commit_group;\n" ::: "memory")
#define CP_WAIT1()  asm volatile("cp.async.wait_group 1;\n" ::: "memory")
#define CP_WAIT0()  asm volatile("cp.async.wait_group 0;\n" ::: "memory")

__device__ __forceinline__ uint32_t smem_u32(const void* p) {
    uint32_t a;
    asm("{ .reg .u64 t; cvta.to.shared.u64 t, %1; cvt.u32.u64 %0, t; }"
        : "=r"(a) : "l"(p));
    return a;
}

__device__ __forceinline__ void ldm_x4(uint32_t* r, uint32_t addr) {
    asm volatile("ldmatrix.sync.aligned.m8n8.x4.shared.b16 {%0,%1,%2,%3}, [%4];"
                 : "=r"(r[0]), "=r"(r[1]), "=r"(r[2]), "=r"(r[3]) : "r"(addr));
}

__device__ __forceinline__ void mma16816h(float* c, const uint32_t* a, const uint32_t* b) {
    asm volatile(
        "mma.sync.aligned.m16n8k16.row.col.f32.f16.f16.f32 "
        "{%0,%1,%2,%3}, {%4,%5,%6,%7}, {%8,%9}, {%0,%1,%2,%3};"
        : "+f"(c[0]), "+f"(c[1]), "+f"(c[2]), "+f"(c[3])
        : "r"(a[0]), "r"(a[1]), "r"(a[2]), "r"(a[3]), "r"(b[0]), "r"(b[1]));
}

// ====================== lin GEMM (fp16, lrelu, dual output) ================
// C = lrelu(A @ B^T + bias): writes S (unscaled, stride sKp, sec0) and
// Sc (dis-scaled gather source, stride Nc).
// stage layout (80B rows): A rows 0-127, B rows 128-191. Stage = 15360B.
#define GSTAGE 15360

__global__ __launch_bounds__(256, 2) void gemm_mma2(
    const __half* __restrict__ A, const __half* __restrict__ B,
    const float* __restrict__ bias, __half* __restrict__ S, int sKp,
    __half* __restrict__ Sc, int M, int Kp, int Nc) {
    extern __shared__ char smem[];
    const uint32_t s0 = smem_u32(smem);
    const int tid = threadIdx.x;
    const int wid = tid >> 5;
    const int lane = tid & 31;
    const int wm = wid & 3, wn = wid >> 2;
    const int bn = blockIdx.x << 6;
    const int bm = blockIdx.y << 7;

    float acc[2][4][4];
#pragma unroll
    for (int i = 0; i < 2; i++)
#pragma unroll
        for (int j = 0; j < 4; j++)
#pragma unroll
            for (int k = 0; k < 4; k++) acc[i][j][k] = 0.f;

#define LOAD_STAGE(stg, kc) do {                                             \
    uint32_t dstBase = s0 + (stg) * GSTAGE;                                  \
    _Pragma("unroll")                                                        \
    for (int u = tid; u < 768; u += 256) {                                   \
        uint32_t d; const char* g;                                           \
        if (u < 512) {                                                       \
            int row = u >> 2, seg = u & 3;                                   \
            d = dstBase + row * 80 + seg * 16;                               \
            g = (const char*)A + ((size_t)(bm + row) * Kp + (kc)) * 2        \
                + seg * 16;                                                  \
        } else {                                                             \
            int t = u - 512; int row = t >> 2, seg = t & 3;                  \
            d = dstBase + (128 + row) * 80 + seg * 16;                       \
            g = (const char*)B + ((size_t)(bn + row) * Kp + (kc)) * 2        \
                + seg * 16;                                                  \
        }                                                                    \
        CP16(d, g);                                                          \
    } } while (0)

    const int nK = Kp >> 5;
    LOAD_STAGE(0, 0);
    CP_COMMIT();
    if (nK > 1) { LOAD_STAGE(1, 32); CP_COMMIT(); }

    for (int kt = 0; kt < nK; kt++) {
        if (kt + 1 < nK) CP_WAIT1(); else CP_WAIT0();
        __syncthreads();
        if (kt + 2 < nK) {
            LOAD_STAGE((kt + 2) % 3, (kt + 2) << 5);
            CP_COMMIT();
        }
        uint32_t base = s0 + (kt % 3) * GSTAGE;
        uint32_t kb = (lane >> 4) * 16;
        uint32_t arow = wm * 32 + (lane & 15);
        uint32_t brow = 128 + wn * 32 + (lane & 15);
#pragma unroll
        for (int kk = 0; kk < 2; kk++) {
            uint32_t a[2][4];
#pragma unroll
            for (int mt = 0; mt < 2; mt++)
                ldm_x4(a[mt], base + (arow + mt * 16) * 80 + kk * 32 + kb);
            uint32_t b[4][2];
#pragma unroll
            for (int j = 0; j < 2; j++) {
                uint32_t r[4];
                ldm_x4(r, base + (brow + j * 16) * 80 + kk * 32 + kb);
                b[2 * j][0] = r[0]; b[2 * j][1] = r[2];
                b[2 * j + 1][0] = r[1]; b[2 * j + 1][1] = r[3];
            }
#pragma unroll
            for (int mt = 0; mt < 2; mt++)
#pragma unroll
                for (int nt = 0; nt < 4; nt++)
                    mma16816h(acc[mt][nt], a[mt], b[nt]);
        }
    }

    const int gid = lane >> 2, tig = lane & 3;
#pragma unroll
    for (int mt = 0; mt < 2; mt++) {
#pragma unroll
        for (int half = 0; half < 2; half++) {
            int row = bm + wm * 32 + mt * 16 + half * 8 + gid;
            bool valid = row < M;
            float dr = valid ? g_dis[row] : 0.f;
#pragma unroll
            for (int nt = 0; nt < 4; nt++) {
                int col = bn + wn * 32 + nt * 8 + tig * 2;
                float v0 = 0.f, v1 = 0.f;
                if (valid) {
                    v0 = acc[mt][nt][2 * half + 0] + bias[col];
                    v1 = acc[mt][nt][2 * half + 1] + bias[col + 1];
                    v0 = v0 > 0.f ? v0 : 0.1f * v0;
                    v1 = v1 > 0.f ? v1 : 0.1f * v1;
                }
                *reinterpret_cast<__half2*>(S + (size_t)row * sKp + col) =
                    __floats2half2_rn(v0, v1);
                if (valid)
                    *reinterpret_cast<__half2*>(Sc + (size_t)row * Nc + col) =
                        __floats2half2_rn(dr * v0, dr * v1);
            }
        }
    }
}

// ====================== fused gate GEMM + gate eval ========================
// stage: A 128 rows + B 3*64 rows, 80B padded = 25600B. 3 stages = 76800B.
#define GSTAGE_G 25600

__global__ __launch_bounds__(256) void gemm_gates(
    const __half* __restrict__ A, const __half* __restrict__ B,
    const float* __restrict__ bias, const float* __restrict__ wcO,
    __half* __restrict__ outY, int M, int Kp, int H) {
    extern __shared__ char smem[];
    const uint32_t s0 = smem_u32(smem);
    const int tid = threadIdx.x;
    const int wid = tid >> 5;
    const int lane = tid & 31;
    const int wm = wid & 3, wn = wid >> 2;
    const int bn = blockIdx.x << 6;
    const int bm = blockIdx.y << 7;

    float accI[2][4][4], accC[2][4][4], accO[2][4][4];
#pragma unroll
    for (int i = 0; i < 2; i++)
#pragma unroll
        for (int j = 0; j < 4; j++)
#pragma unroll
            for (int k = 0; k < 4; k++) {
                accI[i][j][k] = 0.f; accC[i][j][k] = 0.f; accO[i][j][k] = 0.f;
            }

#define LOAD_STAGE_G(stg, kc) do {                                           \
    uint32_t dstBase = s0 + (stg) * GSTAGE_G;                                \
    _Pragma("unroll")                                                        \
    for (int u = tid; u < 1280; u += 256) {                                  \
        uint32_t d; const char* g;                                           \
        if (u < 512) {                                                       \
            int row = u >> 2, seg = u & 3;                                   \
            d = dstBase + row * 80 + seg * 16;                               \
            g = (const char*)A + ((size_t)(bm + row) * Kp + (kc)) * 2        \
                + seg * 16;                                                  \
        } else {                                                             \
            int t = u - 512; int gate = t >> 8; int tt = t & 255;            \
            int row = tt >> 2, seg = tt & 3;                                 \
            d = dstBase + (128 + gate * 64 + row) * 80 + seg * 16;           \
            g = (const char*)B + ((size_t)(gate * H + bn + row) * Kp + (kc)) \
                * 2 + seg * 16;                                              \
        }                                                                    \
        CP16(d, g);                                                          \
    } } while (0)

    const int nK = Kp >> 5;
    LOAD_STAGE_G(0, 0);
    CP_COMMIT();
    if (nK > 1) { LOAD_STAGE_G(1, 32); CP_COMMIT(); }

    for (int kt = 0; kt < nK; kt++) {
        if (kt + 1 < nK) CP_WAIT1(); else CP_WAIT0();
        __syncthreads();
        if (kt + 2 < nK) {
            LOAD_STAGE_G((kt + 2) % 3, (kt + 2) << 5);
            CP_COMMIT();
        }
        uint32_t base = s0 + (kt % 3) * GSTAGE_G;
        uint32_t kb = (lane >> 4) * 16;
        uint32_t arow = wm * 32 + (lane & 15);
#pragma unroll
        for (int kk = 0; kk < 2; kk++) {
            uint32_t a[2][4];
#pragma unroll
            for (int mt = 0; mt < 2; mt++)
                ldm_x4(a[mt], base + (arow + mt * 16) * 80 + kk * 32 + kb);
#pragma unroll
            for (int gate = 0; gate < 3; gate++) {
                uint32_t brow = 128 + gate * 64 + wn * 32 + (lane & 15);
                uint32_t b[4][2];
#pragma unroll
                for (int j = 0; j < 2; j++) {
                    uint32_t r[4];
                    ldm_x4(r, base + (brow + j * 16) * 80 + kk * 32 + kb);
                    b[2 * j][0] = r[0]; b[2 * j][1] = r[2];
                    b[2 * j + 1][0] = r[1]; b[2 * j + 1][1] = r[3];
                }
                float (*acc)[4][4] = gate == 0 ? accI : (gate == 1 ? accC : accO);
#pragma unroll
                for (int mt = 0; mt < 2; mt++)
#pragma unroll
                    for (int nt = 0; nt < 4; nt++)
                        mma16816h(acc[mt][nt], a[mt], b[nt]);
            }
        }
    }

    const int gid = lane >> 2, tig = lane & 3;
#pragma unroll
    for (int mt = 0; mt < 2; mt++) {
#pragma unroll
        for (int half = 0; half < 2; half++) {
            int row = bm + wm * 32 + mt * 16 + half * 8 + gid;
            bool valid = row < M;
#pragma unroll
            for (int nt = 0; nt < 4; nt++) {
                int col = bn + wn * 32 + nt * 8 + tig * 2;
                float y0 = 0.f, y1 = 0.f;
                if (valid) {
                    float vI0 = accI[mt][nt][2 * half + 0] + bias[col];
                    float vI1 = accI[mt][nt][2 * half + 1] + bias[col + 1];
                    float vC0 = accC[mt][nt][2 * half + 0] + bias[H + col];
                    float vC1 = accC[mt][nt][2 * half + 1] + bias[H + col + 1];
                    float vO0 = accO[mt][nt][2 * half + 0] + bias[2 * H + col];
                    float vO1 = accO[mt][nt][2 * half + 1] + bias[2 * H + col + 1];
                    float I0 = fsig(vI0), T0 = ftanh(vC0), Cv0 = I0 * T0;
                    float O0 = fsig(vO0 + wcO[col] * Cv0);
                    y0 = O0 * ftanh(Cv0); y0 = y0 > 0.f ? y0 : 0.1f * y0;
                    float I1 = fsig(vI1), T1 = ftanh(vC1), Cv1 = I1 * T1;
                    float O1 = fsig(vO1 + wcO[col + 1] * Cv1);
                    y1 = O1 * ftanh(Cv1); y1 = y1 > 0.f ? y1 : 0.1f * y1;
                }
                *reinterpret_cast<__half2*>(outY + (size_t)row * H + col) =
                    __floats2half2_rn(y0, y1);
            }
        }
    }
}

// ====================== layer-3 tail: lin3 on fp16 y =======================

__global__ __launch_bounds__(256) void k_lin3h(
    const __half* __restrict__ Y, const float* __restrict__ W,
    const float* __restrict__ b, float* __restrict__ out, int n) {
    __shared__ float sW3[192];
    int tid = threadIdx.x;
    if (tid < 192) sW3[tid] = W[tid];
    __syncthreads();
    int lane = tid & 31, w = tid >> 5;
    for (int rr = 0; rr < 8; rr++) {
        int r = blockIdx.x * 64 + w * 8 + rr;
        if (r >= n) return;
        const __half* y = Y + (size_t)r * 64;
        float p0 = 0.f, p1 = 0.f, p2 = 0.f;
#pragma unroll
        for (int k = 0; k < 2; k++) {
            int u = lane + 32 * k;
            float yv = __half2float(y[u]);
            p0 += yv * sW3[u * 3]; p1 += yv * sW3[u * 3 + 1]; p2 += yv * sW3[u * 3 + 2];
        }
#pragma unroll
        for (int off = 16; off; off >>= 1) {
            p0 += __shfl_xor_sync(0xffffffffu, p0, off);
            p1 += __shfl_xor_sync(0xffffffffu, p1, off);
            p2 += __shfl_xor_sync(0xffffffffu, p2, off);
        }
        if (lane == 0) {
            out[r * 3] = p0 + b[0];
            out[r * 3 + 1] = p1 + b[1];
            out[r * 3 + 2] = p2 + b[2];
        }
    }
}

// ====================== host orchestration =================================

static inline int ceildiv(int a, int b) { return (a + b - 1) / b; }

extern "C" void kernel_launch(void* const* d_in, const int* in_sizes, int n_in,
                              void* d_out, int out_size) {
    const float* x = (const float*)d_in[0];
    const int* ei = (const int*)d_in[1];
    int N = in_sizes[0] / 3;
    int E = in_sizes[1] / 2;
    const int* src = ei;
    const int* dst = ei + E;
    int Npad = (N + 127) & ~127;
    int Mt = Npad / 128;

    const float* l1_Wx = (const float*)d_in[2];
    const float* l1_bx = (const float*)d_in[3];
    const float* l1_bh = (const float*)d_in[5];
    const float* l1_wc = (const float*)d_in[6];
    const float* l1_b  = (const float*)d_in[7];
    const float* l2_Wx = (const float*)d_in[8];
    const float* l2_bx = (const float*)d_in[9];
    const float* l2_bh = (const float*)d_in[11];
    const float* l2_wc = (const float*)d_in[12];
    const float* l2_b  = (const float*)d_in[13];
    const float* l3_Wx = (const float*)d_in[14];
    const float* l3_bx = (const float*)d_in[15];
    const float* l3_bh = (const float*)d_in[17];
    const float* l3_wc = (const float*)d_in[18];
    const float* l3_b  = (const float*)d_in[19];
    const float* lin1_W = (const float*)d_in[20];
    const float* lin1_b = (const float*)d_in[21];
    const float* lin2_W = (const float*)d_in[22];
    const float* lin2_b = (const float*)d_in[23];
    const float* lin3_W = (const float*)d_in[24];
    const float* lin3_b = (const float*)d_in[25];
    float* out = (float*)d_out;

    void* p;
    cudaGetSymbolAddress(&p, g_tmp);   int* tmp = (int*)p;
    cudaGetSymbolAddress(&p, g_t1d);   float* t1d = (float*)p;
    cudaGetSymbolAddress(&p, g_t1s);   float* t1s = (float*)p;
    cudaGetSymbolAddress(&p, g_xA);    __half* xA = (__half*)p;
    cudaGetSymbolAddress(&p, g_xB);    __half* xB = (__half*)p;
    cudaGetSymbolAddress(&p, g_wbias); float* wb = (float*)p;
    cudaGetSymbolAddress(&p, g_bufA);  __half* bufA = (__half*)p;
    cudaGetSymbolAddress(&p, g_bufB);  __half* bufB = (__half*)p;
    cudaGetSymbolAddress(&p, g_bbuf);  __half* bb = (__half*)p;

    cudaFuncSetAttribute(gemm_mma2, cudaFuncAttributeMaxDynamicSharedMemorySize,
                         3 * GSTAGE);
    cudaFuncSetAttribute(gemm_gates, cudaFuncAttributeMaxDynamicSharedMemorySize,
                         3 * GSTAGE_G);

    cudaStream_t s = 0;

    // ---- graph preprocessing ----
    cudaMemsetAsync(tmp, 0, 3 * MAXN * sizeof(int), s);
    k_degree<<<ceildiv(E, 256), 256, 0, s>>>(src, dst, E);
    k_scan<<<1, 1024, 0, s>>>(N);
    k_fill<<<ceildiv(E, 256), 256, 0, s>>>(src, dst, E);
    k_xs<<<ceildiv(N, 256), 256, 0, s>>>(x, N);

    // ---- all weight/bias preprocessing in one kernel ----
    k_prep_all<<<ceildiv(E6, 256), 256, 0, s>>>(
        l1_Wx, l2_Wx, l3_Wx, lin1_W, lin2_W,
        l1_bx, l1_bh, l1_b, l2_bx, l2_bh, l2_b, l3_bx, l3_bh, l3_b);

    // ================= layer 1 (F=3, H=256) — fully fused ===================
    k_l1a<<<ceildiv(N, 256), 256, 0, s>>>(t1d, t1s, N);
    k_l1gates<<<ceildiv(Npad, 64), 256, 0, s>>>(x, t1d, t1s, l1_wc + 512, bufB, N, Npad);
    // lin1: [N,256]@[256,128] + lrelu -> bufA sec0 (T0) + xA (dis-scaled)
    gemm_mma2<<<dim3(2, Mt), 256, 3 * GSTAGE, s>>>(
        bufB, bb + O_BL1, lin1_b, bufA, 384, xA, N, 256, 128);

    // ================= layer 2 (F=128, H=128) =================
    k_spmv_split<128, 0><<<ceildiv(Npad, 8), 256, 0, s>>>(xA, nullptr, xB, bufA, 384, 128, N, Npad);
    k_spmv_split<128, 1><<<ceildiv(Npad, 8), 256, 0, s>>>(xB, bufA, nullptr, bufA, 384, 256, N, Npad);
    gemm_gates<<<dim3(2, Mt), 256, 3 * GSTAGE_G, s>>>(
        bufA, bb + O_B2, wb + 768, l2_wc + 256, bufB, N, 384, 128);
    // lin2: [N,128]@[128,64] + lrelu -> bufA sec0 (Kp=192) + xA (scaled, F=64)
    gemm_mma2<<<dim3(1, Mt), 256, 3 * GSTAGE, s>>>(
        bufB, bb + O_BL2, lin2_b, bufA, 192, xA, N, 128, 64);

    // ================= layer 3 (F=64, H=64) =================
    k_spmv_split<64, 0><<<ceildiv(Npad, 16), 256, 0, s>>>(xA, nullptr, xB, bufA, 192, 64, N, Npad);
    k_spmv_split<64, 1><<<ceildiv(Npad, 16), 256, 0, s>>>(xB, bufA, nullptr, bufA, 192, 128, N, Npad);
    gemm_gates<<<dim3(1, Mt), 256, 3 * GSTAGE_G, s>>>(
        bufA, bb + O_B3, wb + 1152, l3_wc + 128, bufB, N, 192, 64);
    k_lin3h<<<ceildiv(N, 64), 256, 0, s>>>(bufB, lin3_W, lin3_b, out, N);
}

// round 13
// speedup vs baseline: 1.0889x; 1.0889x over previous
#include <cuda_runtime.h>
#include <cuda_fp16.h>
#include <math.h>
#include <stdint.h>

// ---------------- problem-size caps (fixed by setup_inputs) ----------------
#define MAXN 50000
#define NPADMAX 50048   // MAXN rounded up to 128

// ---------------- device scratch (no allocation allowed) -------------------
__device__ int   g_tmp[3 * MAXN];    // deg | cnt | cur (one memset)
__device__ int   g_roff[MAXN + 1];
__device__ int2  g_edge[800000];     // packed (src, weight-bits)
__device__ float g_xc[(size_t)MAXN * 384];     // dense Tx1 scratch (fp16 view) / l1 fp32
__device__ float g_h2[(size_t)MAXN * 128];     // post-linear output (fp16 view)
__device__ float g_wbias[1344];                // combined gate biases (l1|l2|l3)
__device__ float g_w1t[9 * 768];               // layer1 gate weights transposed fp32
__device__ __align__(256) __half g_bufA[(size_t)NPADMAX * 384]; // gconv A (single)
__device__ __align__(256) __half g_bufB[(size_t)NPADMAX * 256]; // lin A / gate-out
__device__ __align__(256) __half g_bbuf[262144];                // weights fp16

// weight buffer element offsets (rows x Kp, single fp16)
#define O_B2  24576    // l2 gate: 384 x 384
#define O_B3  172032   // l3 gate: 192 x 192
#define O_BL1 208896   // lin1: 128 x 256
#define O_BL2 241664   // lin2: 64 x 128

// ====================== graph preprocessing ================================

__global__ void k_degree(const int* __restrict__ src, const int* __restrict__ dst, int E) {
    int e = blockIdx.x * blockDim.x + threadIdx.x;
    if (e >= E) return;
    atomicAdd(&g_tmp[src[e]], 1);            // deg
    atomicAdd(&g_tmp[MAXN + dst[e]], 1);     // cnt
}

__global__ void k_scan(int n) {
    __shared__ int ssum[1024];
    int tid = threadIdx.x;
    const int T = 1024;
    int chunk = (n + T - 1) / T;
    int beg = tid * chunk;
    int end = beg + chunk; if (end > n) end = n;
    int s = 0;
    for (int i = beg; i < end; i++) s += g_tmp[MAXN + i];
    ssum[tid] = s;
    __syncthreads();
    for (int off = 1; off < T; off <<= 1) {
        int v = (tid >= off) ? ssum[tid - off] : 0;
        __syncthreads();
        ssum[tid] += v;
        __syncthreads();
    }
    int run = (tid > 0) ? ssum[tid - 1] : 0;
    for (int i = beg; i < end; i++) { g_roff[i] = run; run += g_tmp[MAXN + i]; }
    if (tid == T - 1) g_roff[n] = ssum[T - 1];
}

__global__ void k_fill(const int* __restrict__ src, const int* __restrict__ dst, int E) {
    int e = blockIdx.x * blockDim.x + threadIdx.x;
    if (e >= E) return;
    int s = src[e], d = dst[e];
    int pos = g_roff[d] + atomicAdd(&g_tmp[2 * MAXN + d], 1);
    int ds = g_tmp[s], dd = g_tmp[d];
    float is = ds > 0 ? rsqrtf((float)ds) : 0.0f;
    float id = dd > 0 ? rsqrtf((float)dd) : 0.0f;
    g_edge[pos] = make_int2(s, __float_as_int(-is * id));
}

// ====================== merged weight/bias preprocessing ===================

__device__ __forceinline__ void prep_gateB(const float* __restrict__ Wx, int F, int H,
                                           int Kp, int nrow, int kk,
                                           __half* __restrict__ dst) {
    int gp = nrow / H, o = nrow % H;
    int gate = (gp == 0) ? 0 : (gp + 1);   // gates {0,2,3}
    float w = 0.0f;
    if (kk < 3 * F) {
        int kc = kk / F, f = kk % F;
        w = Wx[(((size_t)gate * 3 + kc) * F + f) * H + o];
    }
    dst[(size_t)nrow * Kp + kk] = __float2half_rn(w);
}

__device__ __forceinline__ void prep_linB(const float* __restrict__ W, int Hout,
                                          int Kp, int nrow, int kk,
                                          __half* __restrict__ dst) {
    dst[(size_t)nrow * Kp + kk] = __float2half_rn(W[(size_t)kk * Hout + nrow]);
}

#define E1 24576     // 768*32 (layer1 -> transposed fp32 table)
#define E2 172032    // +384*384
#define E3 208896    // +192*192
#define E4 241664    // +128*256
#define E5 249856    // +64*128
#define E6 251200    // +1344 biases

__global__ void k_prep_all(
    const float* __restrict__ w1, const float* __restrict__ w2, const float* __restrict__ w3,
    const float* __restrict__ wl1, const float* __restrict__ wl2,
    const float* __restrict__ bx1, const float* __restrict__ bh1, const float* __restrict__ b1,
    const float* __restrict__ bx2, const float* __restrict__ bh2, const float* __restrict__ b2,
    const float* __restrict__ bx3, const float* __restrict__ bh3, const float* __restrict__ b3) {
    int idx = blockIdx.x * blockDim.x + threadIdx.x;
    if (idx >= E6) return;
    if (idx < E1) {
        int nrow = idx / 32, kk = idx % 32;
        if (kk < 9) {
            int gp = nrow / 256, o = nrow % 256;
            int gate = (gp == 0) ? 0 : (gp + 1);
            int kc = kk / 3, f = kk % 3;
            g_w1t[kk * 768 + nrow] = w1[(((size_t)gate * 3 + kc) * 3 + f) * 256 + o];
        }
    } else if (idx < E2) {
        int t = idx - E1;
        prep_gateB(w2, 128, 128, 384, t / 384, t % 384, g_bbuf + O_B2);
    } else if (idx < E3) {
        int t = idx - E2;
        prep_gateB(w3, 64, 64, 192, t / 192, t % 192, g_bbuf + O_B3);
    } else if (idx < E4) {
        int t = idx - E3;
        prep_linB(wl1, 128, 256, t / 256, t % 256, g_bbuf + O_BL1);
    } else if (idx < E5) {
        int t = idx - E4;
        prep_linB(wl2, 64, 128, t / 128, t % 128, g_bbuf + O_BL2);
    } else {
        int t = idx - E5;
        const float *bx, *bh, *bb; int H, base;
        if (t < 768)       { bx = bx1; bh = bh1; bb = b1; H = 256; base = 0; }
        else if (t < 1152) { bx = bx2; bh = bh2; bb = b2; H = 128; base = 768; t -= 768; }
        else               { bx = bx3; bh = bh3; bb = b3; H = 64;  base = 1152; t -= 1152; }
        int gp = t / H, o = t % H;
        int gate = (gp == 0) ? 0 : (gp + 1);
        g_wbias[base + t] = bx[gate * H + o] + bh[gate * H + o] + bb[gate * H + o];
    }
}

// ====================== fast transcendentals (HW tanh) =====================

__device__ __forceinline__ float ftanh(float x) {
    float y;
    asm("tanh.approx.f32 %0, %1;" : "=f"(y) : "f"(x));
    return y;
}
__device__ __forceinline__ float fsig(float x) {
    return fmaf(ftanh(0.5f * x), 0.5f, 0.5f);
}

// ====================== layer-1: T1 dense pass (unroll-4) ==================

__global__ void k_l1a(const float* __restrict__ x, float* __restrict__ t1d, int n) {
    int row = blockIdx.x * blockDim.x + threadIdx.x;
    if (row >= n) return;
    float t1[3] = {0, 0, 0};
    int j0 = g_roff[row], j1 = g_roff[row + 1];
    int j = j0;
    int jend = j0 + ((j1 - j0) & ~3);
    for (; j < jend; j += 4) {
        int2 e0 = g_edge[j], e1 = g_edge[j + 1], e2 = g_edge[j + 2], e3 = g_edge[j + 3];
        const float* x0 = x + (size_t)e0.x * 3;
        const float* x1 = x + (size_t)e1.x * 3;
        const float* x2 = x + (size_t)e2.x * 3;
        const float* x3 = x + (size_t)e3.x * 3;
        float v00 = x0[0], v01 = x0[1], v02 = x0[2];
        float v10 = x1[0], v11 = x1[1], v12 = x1[2];
        float v20 = x2[0], v21 = x2[1], v22 = x2[2];
        float v30 = x3[0], v31 = x3[1], v32 = x3[2];
        float w0 = __int_as_float(e0.y), w1 = __int_as_float(e1.y);
        float w2 = __int_as_float(e2.y), w3 = __int_as_float(e3.y);
        t1[0] += w0 * v00 + w1 * v10 + w2 * v20 + w3 * v30;
        t1[1] += w0 * v01 + w1 * v11 + w2 * v21 + w3 * v31;
        t1[2] += w0 * v02 + w1 * v12 + w2 * v22 + w3 * v32;
    }
    for (; j < j1; j++) {
        int2 e = g_edge[j];
        float w = __int_as_float(e.y);
        const float* xr = x + (size_t)e.x * 3;
        t1[0] += w * xr[0]; t1[1] += w * xr[1]; t1[2] += w * xr[2];
    }
    t1d[row * 3] = t1[0]; t1d[row * 3 + 1] = t1[1]; t1d[row * 3 + 2] = t1[2];
}

// ====================== layer-1 fused: T2 gather + gates -> bufB ===========

__global__ __launch_bounds__(256) void k_l1gates(
    const float* __restrict__ x, const float* __restrict__ t1d,
    const float* __restrict__ wcO, __half* __restrict__ outA, int n, int npad) {
    __shared__ __half sW[9 * 768];
    __shared__ float sB[768];
    int tid = threadIdx.x;
    for (int i = tid; i < 9 * 768; i += 256) sW[i] = __float2half_rn(g_w1t[i]);
    for (int i = tid; i < 768; i += 256) sB[i] = g_wbias[i];
    __syncthreads();
    const __half2* sW2 = reinterpret_cast<const __half2*>(sW);
    int lane = tid & 31, w = tid >> 5;

    for (int rr = 0; rr < 8; rr++) {
        int r = blockIdx.x * 64 + w * 8 + rr;
        if (r >= npad) return;
        if (r >= n) {
#pragma unroll
            for (int c = 0; c < 4; c++)
                *reinterpret_cast<__half2*>(outA + (size_t)r * 256 + 2 * lane + 64 * c) =
                    __floats2half2_rn(0.f, 0.f);
            continue;
        }
        float p0 = 0.f, p1 = 0.f, p2 = 0.f;
        int j0 = g_roff[r], j1 = g_roff[r + 1];
        for (int j = j0 + lane; j < j1; j += 32) {
            int2 e = g_edge[j];
            float wgt = __int_as_float(e.y);
            const float* tr = t1d + (size_t)e.x * 3;
            p0 += wgt * tr[0]; p1 += wgt * tr[1]; p2 += wgt * tr[2];
        }
#pragma unroll
        for (int off = 16; off; off >>= 1) {
            p0 += __shfl_xor_sync(0xffffffffu, p0, off);
            p1 += __shfl_xor_sync(0xffffffffu, p1, off);
            p2 += __shfl_xor_sync(0xffffffffu, p2, off);
        }
        float a[9];
        a[0] = x[r * 3]; a[1] = x[r * 3 + 1]; a[2] = x[r * 3 + 2];
        a[3] = t1d[r * 3]; a[4] = t1d[r * 3 + 1]; a[5] = t1d[r * 3 + 2];
        a[6] = 2.f * p0 - a[0]; a[7] = 2.f * p1 - a[1]; a[8] = 2.f * p2 - a[2];

        float2 pi[4], pc[4], po[4];
#pragma unroll
        for (int c = 0; c < 4; c++) {
            int u = 2 * lane + 64 * c;
            pi[c] = make_float2(sB[u], sB[u + 1]);
            pc[c] = make_float2(sB[256 + u], sB[256 + u + 1]);
            po[c] = make_float2(sB[512 + u], sB[512 + u + 1]);
        }
#pragma unroll
        for (int k = 0; k < 9; k++) {
            float ak = a[k];
            int kb = k * 384;
#pragma unroll
            for (int c = 0; c < 4; c++) {
                int h2i = lane + 32 * c;
                float2 wi = __half22float2(sW2[kb + h2i]);
                pi[c].x += ak * wi.x; pi[c].y += ak * wi.y;
                float2 wc2 = __half22float2(sW2[kb + 128 + h2i]);
                pc[c].x += ak * wc2.x; pc[c].y += ak * wc2.y;
                float2 wo = __half22float2(sW2[kb + 256 + h2i]);
                po[c].x += ak * wo.x; po[c].y += ak * wo.y;
            }
        }
#pragma unroll
        for (int c = 0; c < 4; c++) {
            int u = 2 * lane + 64 * c;
            float I0 = fsig(pi[c].x), T0 = ftanh(pc[c].x), C0 = I0 * T0;
            float O0 = fsig(po[c].x + wcO[u] * C0);
            float y0 = O0 * ftanh(C0); y0 = y0 > 0.f ? y0 : 0.1f * y0;
            float I1 = fsig(pi[c].y), T1 = ftanh(pc[c].y), C1 = I1 * T1;
            float O1 = fsig(po[c].y + wcO[u + 1] * C1);
            float y1 = O1 * ftanh(C1); y1 = y1 > 0.f ? y1 : 0.1f * y1;
            *reinterpret_cast<__half2*>(outA + (size_t)r * 256 + u) =
                __floats2half2_rn(y0, y1);
        }
    }
}

// ====================== fused SpMV + split (fp16 IO, unroll-4) =============

template <int F, int CHEB2>
__global__ void k_spmv_split(const __half* __restrict__ X, const __half* __restrict__ X0,
                             __half* __restrict__ Yd,
                             __half* __restrict__ A2, int Kp, int sec,
                             int n, int npad) {
    const int TPR = F / 4;
    int tid = threadIdx.x;
    int row = blockIdx.x * (256 / TPR) + tid / TPR;
    int f = (tid % TPR) * 4;
    if (row >= npad) return;
    float a0 = 0.f, a1 = 0.f, a2 = 0.f, a3 = 0.f;
    if (row < n) {
        int j0 = g_roff[row], j1 = g_roff[row + 1];
        int j = j0;
        int jend = j0 + ((j1 - j0) & ~3);
        for (; j < jend; j += 4) {
            int2 e0 = g_edge[j], e1 = g_edge[j + 1];
            int2 e2 = g_edge[j + 2], e3 = g_edge[j + 3];
            float2 r0 = *reinterpret_cast<const float2*>(X + (size_t)e0.x * F + f);
            float2 r1 = *reinterpret_cast<const float2*>(X + (size_t)e1.x * F + f);
            float2 r2 = *reinterpret_cast<const float2*>(X + (size_t)e2.x * F + f);
            float2 r3 = *reinterpret_cast<const float2*>(X + (size_t)e3.x * F + f);
            float w0 = __int_as_float(e0.y), w1 = __int_as_float(e1.y);
            float w2 = __int_as_float(e2.y), w3 = __int_as_float(e3.y);
            {
                float2 f01 = __half22float2(*reinterpret_cast<__half2*>(&r0.x));
                float2 f23 = __half22float2(*reinterpret_cast<__half2*>(&r0.y));
                a0 += w0 * f01.x; a1 += w0 * f01.y; a2 += w0 * f23.x; a3 += w0 * f23.y;
            }
            {
                float2 f01 = __half22float2(*reinterpret_cast<__half2*>(&r1.x));
                float2 f23 = __half22float2(*reinterpret_cast<__half2*>(&r1.y));
                a0 += w1 * f01.x; a1 += w1 * f01.y; a2 += w1 * f23.x; a3 += w1 * f23.y;
            }
            {
                float2 f01 = __half22float2(*reinterpret_cast<__half2*>(&r2.x));
                float2 f23 = __half22float2(*reinterpret_cast<__half2*>(&r2.y));
                a0 += w2 * f01.x; a1 += w2 * f01.y; a2 += w2 * f23.x; a3 += w2 * f23.y;
            }
            {
                float2 f01 = __half22float2(*reinterpret_cast<__half2*>(&r3.x));
                float2 f23 = __half22float2(*reinterpret_cast<__half2*>(&r3.y));
                a0 += w3 * f01.x; a1 += w3 * f01.y; a2 += w3 * f23.x; a3 += w3 * f23.y;
            }
        }
        for (; j < j1; j++) {
            int2 e = g_edge[j];
            float w = __int_as_float(e.y);
            float2 raw = *reinterpret_cast<const float2*>(X + (size_t)e.x * F + f);
            float2 f01 = __half22float2(*reinterpret_cast<__half2*>(&raw.x));
            float2 f23 = __half22float2(*reinterpret_cast<__half2*>(&raw.y));
            a0 += w * f01.x; a1 += w * f01.y; a2 += w * f23.x; a3 += w * f23.y;
        }
        if (CHEB2) {
            float2 raw = *reinterpret_cast<const float2*>(X0 + (size_t)row * F + f);
            float2 f01 = __half22float2(*reinterpret_cast<__half2*>(&raw.x));
            float2 f23 = __half22float2(*reinterpret_cast<__half2*>(&raw.y));
            a0 = 2.f * a0 - f01.x; a1 = 2.f * a1 - f01.y;
            a2 = 2.f * a2 - f23.x; a3 = 2.f * a3 - f23.y;
        }
    }
    float2 packed;
    *reinterpret_cast<__half2*>(&packed.x) = __floats2half2_rn(a0, a1);
    *reinterpret_cast<__half2*>(&packed.y) = __floats2half2_rn(a2, a3);
    if (Yd && row < n)
        *reinterpret_cast<float2*>(Yd + (size_t)row * F + f) = packed;
    *reinterpret_cast<float2*>(A2 + (size_t)row * Kp + sec + f) = packed;
}

// ====================== mma.sync common helpers ============================

#define CP16(dst, src) \
    asm volatile("cp.async.ca.shared.global [%0], [%1], 16;\n" :: "r"(dst), "l"(src))
#define CP_COMMIT() asm volatile("cp.async.commit_group;\n" ::: "memory")
#define CP_WAIT1()  asm volatile("cp.async.wait_group 1;\n" ::: "memory")
#define CP_WAIT0()  asm volatile("cp.async.wait_group 0;\n" ::: "memory")

__device__ __forceinline__ uint32_t smem_u32(const void* p) {
    uint32_t a;
    asm("{ .reg .u64 t; cvta.to.shared.u64 t, %1; cvt.u32.u64 %0, t; }"
        : "=r"(a) : "l"(p));
    return a;
}

__device__ __forceinline__ void ldm_x4(uint32_t* r, uint32_t addr) {
    asm volatile("ldmatrix.sync.aligned.m8n8.x4.shared.b16 {%0,%1,%2,%3}, [%4];"
                 : "=r"(r[0]), "=r"(r[1]), "=r"(r[2]), "=r"(r[3]) : "r"(addr));
}

__device__ __forceinline__ void mma16816h(float* c, const uint32_t* a, const uint32_t* b) {
    asm volatile(
        "mma.sync.aligned.m16n8k16.row.col.f32.f16.f16.f32 "
        "{%0,%1,%2,%3}, {%4,%5,%6,%7}, {%8,%9}, {%0,%1,%2,%3};"
        : "+f"(c[0]), "+f"(c[1]), "+f"(c[2]), "+f"(c[3])
        : "r"(a[0]), "r"(a[1]), "r"(a[2]), "r"(a[3]), "r"(b[0]), "r"(b[1]));
}

// ====================== plain fp16 GEMM (lin layers) =======================
// stage layout (80B rows): A rows 0-127, B rows 128-191. Stage = 15360B.
#define GSTAGE 15360

__global__ __launch_bounds__(256, 2) void gemm_mma2(
    const __half* __restrict__ A, const __half* __restrict__ B,
    const float* __restrict__ bias, void* __restrict__ Cout, int halfOut,
    __half* __restrict__ S, int sKp,
    int M, int Kp, int Nc, int act) {
    extern __shared__ char smem[];
    const uint32_t s0 = smem_u32(smem);
    const int tid = threadIdx.x;
    const int wid = tid >> 5;
    const int lane = tid & 31;
    const int wm = wid & 3, wn = wid >> 2;
    const int bn = blockIdx.x << 6;
    const int bm = blockIdx.y << 7;

    float acc[2][4][4];
#pragma unroll
    for (int i = 0; i < 2; i++)
#pragma unroll
        for (int j = 0; j < 4; j++)
#pragma unroll
            for (int k = 0; k < 4; k++) acc[i][j][k] = 0.f;

#define LOAD_STAGE(stg, kc) do {                                             \
    uint32_t dstBase = s0 + (stg) * GSTAGE;                                  \
    _Pragma("unroll")                                                        \
    for (int u = tid; u < 768; u += 256) {                                   \
        uint32_t d; const char* g;                                           \
        if (u < 512) {                                                       \
            int row = u >> 2, seg = u & 3;                                   \
            d = dstBase + row * 80 + seg * 16;                               \
            g = (const char*)A + ((size_t)(bm + row) * Kp + (kc)) * 2        \
                + seg * 16;                                                  \
        } else {                                                             \
            int t = u - 512; int row = t >> 2, seg = t & 3;                  \
            d = dstBase + (128 + row) * 80 + seg * 16;                       \
            g = (const char*)B + ((size_t)(bn + row) * Kp + (kc)) * 2        \
                + seg * 16;                                                  \
        }                                                                    \
        CP16(d, g);                                                          \
    } } while (0)

    const int nK = Kp >> 5;
    LOAD_STAGE(0, 0);
    CP_COMMIT();
    if (nK > 1) { LOAD_STAGE(1, 32); CP_COMMIT(); }

    for (int kt = 0; kt < nK; kt++) {
        if (kt + 1 < nK) CP_WAIT1(); else CP_WAIT0();
        __syncthreads();
        if (kt + 2 < nK) {
            LOAD_STAGE((kt + 2) % 3, (kt + 2) << 5);
            CP_COMMIT();
        }
        uint32_t base = s0 + (kt % 3) * GSTAGE;
        uint32_t kb = (lane >> 4) * 16;
        uint32_t arow = wm * 32 + (lane & 15);
        uint32_t brow = 128 + wn * 32 + (lane & 15);
#pragma unroll
        for (int kk = 0; kk < 2; kk++) {
            uint32_t a[2][4];
#pragma unroll
            for (int mt = 0; mt < 2; mt++)
                ldm_x4(a[mt], base + (arow + mt * 16) * 80 + kk * 32 + kb);
            uint32_t b[4][2];
#pragma unroll
            for (int j = 0; j < 2; j++) {
                uint32_t r[4];
                ldm_x4(r, base + (brow + j * 16) * 80 + kk * 32 + kb);
                b[2 * j][0] = r[0]; b[2 * j][1] = r[2];
                b[2 * j + 1][0] = r[1]; b[2 * j + 1][1] = r[3];
            }
#pragma unroll
            for (int mt = 0; mt < 2; mt++)
#pragma unroll
                for (int nt = 0; nt < 4; nt++)
                    mma16816h(acc[mt][nt], a[mt], b[nt]);
        }
    }

    const int gid = lane >> 2, tig = lane & 3;
#pragma unroll
    for (int mt = 0; mt < 2; mt++) {
#pragma unroll
        for (int half = 0; half < 2; half++) {
            int row = bm + wm * 32 + mt * 16 + half * 8 + gid;
            bool valid = row < M;
#pragma unroll
            for (int nt = 0; nt < 4; nt++) {
                int col = bn + wn * 32 + nt * 8 + tig * 2;
                float v0 = 0.f, v1 = 0.f;
                if (valid) {
                    v0 = acc[mt][nt][2 * half + 0] + bias[col];
                    v1 = acc[mt][nt][2 * half + 1] + bias[col + 1];
                    if (act) {
                        v0 = v0 > 0.f ? v0 : 0.1f * v0;
                        v1 = v1 > 0.f ? v1 : 0.1f * v1;
                    }
                    if (halfOut) {
                        *reinterpret_cast<__half2*>(
                            (__half*)Cout + (size_t)row * Nc + col) =
                            __floats2half2_rn(v0, v1);
                    } else {
                        *reinterpret_cast<float2*>(
                            (float*)Cout + (size_t)row * Nc + col) =
                            make_float2(v0, v1);
                    }
                }
                if (S) {
                    *reinterpret_cast<__half2*>(S + (size_t)row * sKp + col) =
                        __floats2half2_rn(v0, v1);
                }
            }
        }
    }
}

// ====================== fused gate GEMM + gate eval ========================
// stage: A 128 rows + B 3*64 rows, 80B padded = 25600B. 3 stages = 76800B.
#define GSTAGE_G 25600

__global__ __launch_bounds__(256) void gemm_gates(
    const __half* __restrict__ A, const __half* __restrict__ B,
    const float* __restrict__ bias, const float* __restrict__ wcO,
    __half* __restrict__ outY, int M, int Kp, int H) {
    extern __shared__ char smem[];
    const uint32_t s0 = smem_u32(smem);
    const int tid = threadIdx.x;
    const int wid = tid >> 5;
    const int lane = tid & 31;
    const int wm = wid & 3, wn = wid >> 2;
    const int bn = blockIdx.x << 6;
    const int bm = blockIdx.y << 7;

    float accI[2][4][4], accC[2][4][4], accO[2][4][4];
#pragma unroll
    for (int i = 0; i < 2; i++)
#pragma unroll
        for (int j = 0; j < 4; j++)
#pragma unroll
            for (int k = 0; k < 4; k++) {
                accI[i][j][k] = 0.f; accC[i][j][k] = 0.f; accO[i][j][k] = 0.f;
            }

#define LOAD_STAGE_G(stg, kc) do {                                           \
    uint32_t dstBase = s0 + (stg) * GSTAGE_G;                                \
    _Pragma("unroll")                                                        \
    for (int u = tid; u < 1280; u += 256) {                                  \
        uint32_t d; const char* g;                                           \
        if (u < 512) {                                                       \
            int row = u >> 2, seg = u & 3;                                   \
            d = dstBase + row * 80 + seg * 16;                               \
            g = (const char*)A + ((size_t)(bm + row) * Kp + (kc)) * 2        \
                + seg * 16;                                                  \
        } else {                                                             \
            int t = u - 512; int gate = t >> 8; int tt = t & 255;            \
            int row = tt >> 2, seg = tt & 3;                                 \
            d = dstBase + (128 + gate * 64 + row) * 80 + seg * 16;           \
            g = (const char*)B + ((size_t)(gate * H + bn + row) * Kp + (kc)) \
                * 2 + seg * 16;                                              \
        }                                                                    \
        CP16(d, g);                                                          \
    } } while (0)

    const int nK = Kp >> 5;
    LOAD_STAGE_G(0, 0);
    CP_COMMIT();
    if (nK > 1) { LOAD_STAGE_G(1, 32); CP_COMMIT(); }

    for (int kt = 0; kt < nK; kt++) {
        if (kt + 1 < nK) CP_WAIT1(); else CP_WAIT0();
        __syncthreads();
        if (kt + 2 < nK) {
            LOAD_STAGE_G((kt + 2) % 3, (kt + 2) << 5);
            CP_COMMIT();
        }
        uint32_t base = s0 + (kt % 3) * GSTAGE_G;
        uint32_t kb = (lane >> 4) * 16;
        uint32_t arow = wm * 32 + (lane & 15);
#pragma unroll
        for (int kk = 0; kk < 2; kk++) {
            uint32_t a[2][4];
#pragma unroll
            for (int mt = 0; mt < 2; mt++)
                ldm_x4(a[mt], base + (arow + mt * 16) * 80 + kk * 32 + kb);
#pragma unroll
            for (int gate = 0; gate < 3; gate++) {
                uint32_t brow = 128 + gate * 64 + wn * 32 + (lane & 15);
                uint32_t b[4][2];
#pragma unroll
                for (int j = 0; j < 2; j++) {
                    uint32_t r[4];
                    ldm_x4(r, base + (brow + j * 16) * 80 + kk * 32 + kb);
                    b[2 * j][0] = r[0]; b[2 * j][1] = r[2];
                    b[2 * j + 1][0] = r[1]; b[2 * j + 1][1] = r[3];
                }
                float (*acc)[4][4] = gate == 0 ? accI : (gate == 1 ? accC : accO);
#pragma unroll
                for (int mt = 0; mt < 2; mt++)
#pragma unroll
                    for (int nt = 0; nt < 4; nt++)
                        mma16816h(acc[mt][nt], a[mt], b[nt]);
            }
        }
    }

    const int gid = lane >> 2, tig = lane & 3;
#pragma unroll
    for (int mt = 0; mt < 2; mt++) {
#pragma unroll
        for (int half = 0; half < 2; half++) {
            int row = bm + wm * 32 + mt * 16 + half * 8 + gid;
            bool valid = row < M;
#pragma unroll
            for (int nt = 0; nt < 4; nt++) {
                int col = bn + wn * 32 + nt * 8 + tig * 2;
                float y0 = 0.f, y1 = 0.f;
                if (valid) {
                    float vI0 = accI[mt][nt][2 * half + 0] + bias[col];
                    float vI1 = accI[mt][nt][2 * half + 1] + bias[col + 1];
                    float vC0 = accC[mt][nt][2 * half + 0] + bias[H + col];
                    float vC1 = accC[mt][nt][2 * half + 1] + bias[H + col + 1];
                    float vO0 = accO[mt][nt][2 * half + 0] + bias[2 * H + col];
                    float vO1 = accO[mt][nt][2 * half + 1] + bias[2 * H + col + 1];
                    float I0 = fsig(vI0), T0 = ftanh(vC0), Cv0 = I0 * T0;
                    float O0 = fsig(vO0 + wcO[col] * Cv0);
                    y0 = O0 * ftanh(Cv0); y0 = y0 > 0.f ? y0 : 0.1f * y0;
                    float I1 = fsig(vI1), T1 = ftanh(vC1), Cv1 = I1 * T1;
                    float O1 = fsig(vO1 + wcO[col + 1] * Cv1);
                    y1 = O1 * ftanh(Cv1); y1 = y1 > 0.f ? y1 : 0.1f * y1;
                }
                *reinterpret_cast<__half2*>(outY + (size_t)row * H + col) =
                    __floats2half2_rn(y0, y1);
            }
        }
    }
}

// ====================== layer-3 tail: lin3 on fp16 y =======================

__global__ __launch_bounds__(256) void k_lin3h(
    const __half* __restrict__ Y, const float* __restrict__ W,
    const float* __restrict__ b, float* __restrict__ out, int n) {
    __shared__ float sW3[192];
    int tid = threadIdx.x;
    if (tid < 192) sW3[tid] = W[tid];
    __syncthreads();
    int lane = tid & 31, w = tid >> 5;
    for (int rr = 0; rr < 8; rr++) {
        int r = blockIdx.x * 64 + w * 8 + rr;
        if (r >= n) return;
        const __half* y = Y + (size_t)r * 64;
        float p0 = 0.f, p1 = 0.f, p2 = 0.f;
#pragma unroll
        for (int k = 0; k < 2; k++) {
            int u = lane + 32 * k;
            float yv = __half2float(y[u]);
            p0 += yv * sW3[u * 3]; p1 += yv * sW3[u * 3 + 1]; p2 += yv * sW3[u * 3 + 2];
        }
#pragma unroll
        for (int off = 16; off; off >>= 1) {
            p0 += __shfl_xor_sync(0xffffffffu, p0, off);
            p1 += __shfl_xor_sync(0xffffffffu, p1, off);
            p2 += __shfl_xor_sync(0xffffffffu, p2, off);
        }
        if (lane == 0) {
            out[r * 3] = p0 + b[0];
            out[r * 3 + 1] = p1 + b[1];
            out[r * 3 + 2] = p2 + b[2];
        }
    }
}

// ====================== host orchestration =================================

static inline int ceildiv(int a, int b) { return (a + b - 1) / b; }

extern "C" void kernel_launch(void* const* d_in, const int* in_sizes, int n_in,
                              void* d_out, int out_size) {
    const float* x = (const float*)d_in[0];
    const int* ei = (const int*)d_in[1];
    int N = in_sizes[0] / 3;
    int E = in_sizes[1] / 2;
    const int* src = ei;
    const int* dst = ei + E;
    int Npad = (N + 127) & ~127;
    int Mt = Npad / 128;

    const float* l1_Wx = (const float*)d_in[2];
    const float* l1_bx = (const float*)d_in[3];
    const float* l1_bh = (const float*)d_in[5];
    const float* l1_wc = (const float*)d_in[6];
    const float* l1_b  = (const float*)d_in[7];
    const float* l2_Wx = (const float*)d_in[8];
    const float* l2_bx = (const float*)d_in[9];
    const float* l2_bh = (const float*)d_in[11];
    const float* l2_wc = (const float*)d_in[12];
    const float* l2_b  = (const float*)d_in[13];
    const float* l3_Wx = (const float*)d_in[14];
    const float* l3_bx = (const float*)d_in[15];
    const float* l3_bh = (const float*)d_in[17];
    const float* l3_wc = (const float*)d_in[18];
    const float* l3_b  = (const float*)d_in[19];
    const float* lin1_W = (const float*)d_in[20];
    const float* lin1_b = (const float*)d_in[21];
    const float* lin2_W = (const float*)d_in[22];
    const float* lin2_b = (const float*)d_in[23];
    const float* lin3_W = (const float*)d_in[24];
    const float* lin3_b = (const float*)d_in[25];
    float* out = (float*)d_out;

    void* p;
    cudaGetSymbolAddress(&p, g_tmp);   int* tmp = (int*)p;
    cudaGetSymbolAddress(&p, g_xc);    float* xcf = (float*)p;
    __half* xch = (__half*)xcf;
    cudaGetSymbolAddress(&p, g_h2);    __half* H2 = (__half*)p;
    cudaGetSymbolAddress(&p, g_wbias); float* wb = (float*)p;
    cudaGetSymbolAddress(&p, g_bufA);  __half* bufA = (__half*)p;
    cudaGetSymbolAddress(&p, g_bufB);  __half* bufB = (__half*)p;
    cudaGetSymbolAddress(&p, g_bbuf);  __half* bb = (__half*)p;

    cudaFuncSetAttribute(gemm_mma2, cudaFuncAttributeMaxDynamicSharedMemorySize,
                         3 * GSTAGE);
    cudaFuncSetAttribute(gemm_gates, cudaFuncAttributeMaxDynamicSharedMemorySize,
                         3 * GSTAGE_G);

    cudaStream_t s = 0;

    // ---- graph preprocessing ----
    cudaMemsetAsync(tmp, 0, 3 * MAXN * sizeof(int), s);
    k_degree<<<ceildiv(E, 256), 256, 0, s>>>(src, dst, E);
    k_scan<<<1, 1024, 0, s>>>(N);
    k_fill<<<ceildiv(E, 256), 256, 0, s>>>(src, dst, E);

    // ---- all weight/bias preprocessing in one kernel ----
    k_prep_all<<<ceildiv(E6, 256), 256, 0, s>>>(
        l1_Wx, l2_Wx, l3_Wx, lin1_W, lin2_W,
        l1_bx, l1_bh, l1_b, l2_bx, l2_bh, l2_b, l3_bx, l3_bh, l3_b);

    // ================= layer 1 (F=3, H=256) — fully fused ===================
    k_l1a<<<ceildiv(N, 256), 256, 0, s>>>(x, xcf, N);
    k_l1gates<<<ceildiv(Npad, 64), 256, 0, s>>>(x, xcf, l1_wc + 512, bufB, N, Npad);
    // lin1: [N,256]@[256,128] + lrelu -> fp16 H2 + T0 section of layer2 A
    gemm_mma2<<<dim3(128 / 64, Mt), 256, 3 * GSTAGE, s>>>(
        bufB, bb + O_BL1, lin1_b, H2, 1, bufA, 384, N, 256, 128, 1);

    // ================= layer 2 (F=128, H=128) =================
    k_spmv_split<128, 0><<<ceildiv(Npad, 8), 256, 0, s>>>(H2, nullptr, xch, bufA, 384, 128, N, Npad);
    k_spmv_split<128, 1><<<ceildiv(Npad, 8), 256, 0, s>>>(xch, H2, nullptr, bufA, 384, 256, N, Npad);
    // fused gate GEMM + gate eval -> bufB [Npad, 128] fp16
    gemm_gates<<<dim3(2, Mt), 256, 3 * GSTAGE_G, s>>>(
        bufA, bb + O_B2, wb + 768, l2_wc + 256, bufB, N, 384, 128);
    // lin2: [N,128]@[128,64] + lrelu -> fp16 H2 + T0 section of layer3 A
    gemm_mma2<<<dim3(64 / 64, Mt), 256, 3 * GSTAGE, s>>>(
        bufB, bb + O_BL2, lin2_b, H2, 1, bufA, 192, N, 128, 64, 1);

    // ================= layer 3 (F=64, H=64) =================
    k_spmv_split<64, 0><<<ceildiv(Npad, 16), 256, 0, s>>>(H2, nullptr, xch, bufA, 192, 64, N, Npad);
    k_spmv_split<64, 1><<<ceildiv(Npad, 16), 256, 0, s>>>(xch, H2, nullptr, bufA, 192, 128, N, Npad);
    // fused gate GEMM + gate eval -> bufB [Npad, 64] fp16
    gemm_gates<<<dim3(1, Mt), 256, 3 * GSTAGE_G, s>>>(
        bufA, bb + O_B3, wb + 1152, l3_wc + 128, bufB, N, 192, 64);
    k_lin3h<<<ceildiv(N, 64), 256, 0, s>>>(bufB, lin3_W, lin3_b, out, N);
}

// round 14
// speedup vs baseline: 1.1054x; 1.0152x over previous
#include <cuda_runtime.h>
#include <cuda_fp16.h>
#include <math.h>
#include <stdint.h>

// ---------------- problem-size caps (fixed by setup_inputs) ----------------
#define MAXN 50000
#define NPADMAX 50048   // MAXN rounded up to 128

// ---------------- device scratch (no allocation allowed) -------------------
__device__ int   g_tmp[3 * MAXN];    // deg | cnt | cur (one memset)
__device__ int   g_roff[MAXN + 1];
__device__ int2  g_edge[800000];     // packed (src, weight-bits)
__device__ float g_xc[(size_t)MAXN * 384];     // T1 buffer (fp16 view) / l1 fp32
__device__ float g_h2[(size_t)MAXN * 128];     // T0 buffer (fp16 view)
__device__ float g_wbias[1344];                // combined gate biases (l1|l2|l3)
__device__ float g_w1t[9 * 768];               // layer1 gate weights transposed fp32
__device__ __align__(256) __half g_t2buf[(size_t)NPADMAX * 128]; // T2 buffer
__device__ __align__(256) __half g_bufB[(size_t)NPADMAX * 256];  // lin A / gate-out
__device__ __align__(256) __half g_bbuf[262144];                 // weights fp16

// weight buffer element offsets (rows x Kp, single fp16)
#define O_B2  24576    // l2 gate: 384 x 384
#define O_B3  172032   // l3 gate: 192 x 192
#define O_BL1 208896   // lin1: 128 x 256
#define O_BL2 241664   // lin2: 64 x 128

// ====================== graph preprocessing ================================

__global__ void k_degree(const int* __restrict__ src, const int* __restrict__ dst, int E) {
    int e = blockIdx.x * blockDim.x + threadIdx.x;
    if (e >= E) return;
    atomicAdd(&g_tmp[src[e]], 1);            // deg
    atomicAdd(&g_tmp[MAXN + dst[e]], 1);     // cnt
}

__global__ void k_scan(int n) {
    __shared__ int ssum[1024];
    int tid = threadIdx.x;
    const int T = 1024;
    int chunk = (n + T - 1) / T;
    int beg = tid * chunk;
    int end = beg + chunk; if (end > n) end = n;
    int s = 0;
    for (int i = beg; i < end; i++) s += g_tmp[MAXN + i];
    ssum[tid] = s;
    __syncthreads();
    for (int off = 1; off < T; off <<= 1) {
        int v = (tid >= off) ? ssum[tid - off] : 0;
        __syncthreads();
        ssum[tid] += v;
        __syncthreads();
    }
    int run = (tid > 0) ? ssum[tid - 1] : 0;
    for (int i = beg; i < end; i++) { g_roff[i] = run; run += g_tmp[MAXN + i]; }
    if (tid == T - 1) g_roff[n] = ssum[T - 1];
}

__global__ void k_fill(const int* __restrict__ src, const int* __restrict__ dst, int E) {
    int e = blockIdx.x * blockDim.x + threadIdx.x;
    if (e >= E) return;
    int s = src[e], d = dst[e];
    int pos = g_roff[d] + atomicAdd(&g_tmp[2 * MAXN + d], 1);
    int ds = g_tmp[s], dd = g_tmp[d];
    float is = ds > 0 ? rsqrtf((float)ds) : 0.0f;
    float id = dd > 0 ? rsqrtf((float)dd) : 0.0f;
    g_edge[pos] = make_int2(s, __float_as_int(-is * id));
}

// ====================== merged weight/bias preprocessing ===================

__device__ __forceinline__ void prep_gateB(const float* __restrict__ Wx, int F, int H,
                                           int Kp, int nrow, int kk,
                                           __half* __restrict__ dst) {
    int gp = nrow / H, o = nrow % H;
    int gate = (gp == 0) ? 0 : (gp + 1);   // gates {0,2,3}
    float w = 0.0f;
    if (kk < 3 * F) {
        int kc = kk / F, f = kk % F;
        w = Wx[(((size_t)gate * 3 + kc) * F + f) * H + o];
    }
    dst[(size_t)nrow * Kp + kk] = __float2half_rn(w);
}

__device__ __forceinline__ void prep_linB(const float* __restrict__ W, int Hout,
                                          int Kp, int nrow, int kk,
                                          __half* __restrict__ dst) {
    dst[(size_t)nrow * Kp + kk] = __float2half_rn(W[(size_t)kk * Hout + nrow]);
}

#define E1 24576     // 768*32 (layer1 -> transposed fp32 table)
#define E2 172032    // +384*384
#define E3 208896    // +192*192
#define E4 241664    // +128*256
#define E5 249856    // +64*128
#define E6 251200    // +1344 biases

__global__ void k_prep_all(
    const float* __restrict__ w1, const float* __restrict__ w2, const float* __restrict__ w3,
    const float* __restrict__ wl1, const float* __restrict__ wl2,
    const float* __restrict__ bx1, const float* __restrict__ bh1, const float* __restrict__ b1,
    const float* __restrict__ bx2, const float* __restrict__ bh2, const float* __restrict__ b2,
    const float* __restrict__ bx3, const float* __restrict__ bh3, const float* __restrict__ b3) {
    int idx = blockIdx.x * blockDim.x + threadIdx.x;
    if (idx >= E6) return;
    if (idx < E1) {
        int nrow = idx / 32, kk = idx % 32;
        if (kk < 9) {
            int gp = nrow / 256, o = nrow % 256;
            int gate = (gp == 0) ? 0 : (gp + 1);
            int kc = kk / 3, f = kk % 3;
            g_w1t[kk * 768 + nrow] = w1[(((size_t)gate * 3 + kc) * 3 + f) * 256 + o];
        }
    } else if (idx < E2) {
        int t = idx - E1;
        prep_gateB(w2, 128, 128, 384, t / 384, t % 384, g_bbuf + O_B2);
    } else if (idx < E3) {
        int t = idx - E2;
        prep_gateB(w3, 64, 64, 192, t / 192, t % 192, g_bbuf + O_B3);
    } else if (idx < E4) {
        int t = idx - E3;
        prep_linB(wl1, 128, 256, t / 256, t % 256, g_bbuf + O_BL1);
    } else if (idx < E5) {
        int t = idx - E4;
        prep_linB(wl2, 64, 128, t / 128, t % 128, g_bbuf + O_BL2);
    } else {
        int t = idx - E5;
        const float *bx, *bh, *bb; int H, base;
        if (t < 768)       { bx = bx1; bh = bh1; bb = b1; H = 256; base = 0; }
        else if (t < 1152) { bx = bx2; bh = bh2; bb = b2; H = 128; base = 768; t -= 768; }
        else               { bx = bx3; bh = bh3; bb = b3; H = 64;  base = 1152; t -= 1152; }
        int gp = t / H, o = t % H;
        int gate = (gp == 0) ? 0 : (gp + 1);
        g_wbias[base + t] = bx[gate * H + o] + bh[gate * H + o] + bb[gate * H + o];
    }
}

// ====================== fast transcendentals (HW tanh) =====================

__device__ __forceinline__ float ftanh(float x) {
    float y;
    asm("tanh.approx.f32 %0, %1;" : "=f"(y) : "f"(x));
    return y;
}
__device__ __forceinline__ float fsig(float x) {
    return fmaf(ftanh(0.5f * x), 0.5f, 0.5f);
}

// ====================== layer-1: T1 dense pass (unroll-4) ==================

__global__ void k_l1a(const float* __restrict__ x, float* __restrict__ t1d, int n) {
    int row = blockIdx.x * blockDim.x + threadIdx.x;
    if (row >= n) return;
    float t1[3] = {0, 0, 0};
    int j0 = g_roff[row], j1 = g_roff[row + 1];
    int j = j0;
    int jend = j0 + ((j1 - j0) & ~3);
    for (; j < jend; j += 4) {
        int2 e0 = g_edge[j], e1 = g_edge[j + 1], e2 = g_edge[j + 2], e3 = g_edge[j + 3];
        const float* x0 = x + (size_t)e0.x * 3;
        const float* x1 = x + (size_t)e1.x * 3;
        const float* x2 = x + (size_t)e2.x * 3;
        const float* x3 = x + (size_t)e3.x * 3;
        float v00 = x0[0], v01 = x0[1], v02 = x0[2];
        float v10 = x1[0], v11 = x1[1], v12 = x1[2];
        float v20 = x2[0], v21 = x2[1], v22 = x2[2];
        float v30 = x3[0], v31 = x3[1], v32 = x3[2];
        float w0 = __int_as_float(e0.y), w1 = __int_as_float(e1.y);
        float w2 = __int_as_float(e2.y), w3 = __int_as_float(e3.y);
        t1[0] += w0 * v00 + w1 * v10 + w2 * v20 + w3 * v30;
        t1[1] += w0 * v01 + w1 * v11 + w2 * v21 + w3 * v31;
        t1[2] += w0 * v02 + w1 * v12 + w2 * v22 + w3 * v32;
    }
    for (; j < j1; j++) {
        int2 e = g_edge[j];
        float w = __int_as_float(e.y);
        const float* xr = x + (size_t)e.x * 3;
        t1[0] += w * xr[0]; t1[1] += w * xr[1]; t1[2] += w * xr[2];
    }
    t1d[row * 3] = t1[0]; t1d[row * 3 + 1] = t1[1]; t1d[row * 3 + 2] = t1[2];
}

// ====================== layer-1 fused: T2 gather + gates -> bufB ===========

__global__ __launch_bounds__(256) void k_l1gates(
    const float* __restrict__ x, const float* __restrict__ t1d,
    const float* __restrict__ wcO, __half* __restrict__ outA, int n, int npad) {
    __shared__ __half sW[9 * 768];
    __shared__ float sB[768];
    int tid = threadIdx.x;
    for (int i = tid; i < 9 * 768; i += 256) sW[i] = __float2half_rn(g_w1t[i]);
    for (int i = tid; i < 768; i += 256) sB[i] = g_wbias[i];
    __syncthreads();
    const __half2* sW2 = reinterpret_cast<const __half2*>(sW);
    int lane = tid & 31, w = tid >> 5;

    for (int rr = 0; rr < 8; rr++) {
        int r = blockIdx.x * 64 + w * 8 + rr;
        if (r >= npad) return;
        if (r >= n) {
#pragma unroll
            for (int c = 0; c < 4; c++)
                *reinterpret_cast<__half2*>(outA + (size_t)r * 256 + 2 * lane + 64 * c) =
                    __floats2half2_rn(0.f, 0.f);
            continue;
        }
        float p0 = 0.f, p1 = 0.f, p2 = 0.f;
        int j0 = g_roff[r], j1 = g_roff[r + 1];
        for (int j = j0 + lane; j < j1; j += 32) {
            int2 e = g_edge[j];
            float wgt = __int_as_float(e.y);
            const float* tr = t1d + (size_t)e.x * 3;
            p0 += wgt * tr[0]; p1 += wgt * tr[1]; p2 += wgt * tr[2];
        }
#pragma unroll
        for (int off = 16; off; off >>= 1) {
            p0 += __shfl_xor_sync(0xffffffffu, p0, off);
            p1 += __shfl_xor_sync(0xffffffffu, p1, off);
            p2 += __shfl_xor_sync(0xffffffffu, p2, off);
        }
        float a[9];
        a[0] = x[r * 3]; a[1] = x[r * 3 + 1]; a[2] = x[r * 3 + 2];
        a[3] = t1d[r * 3]; a[4] = t1d[r * 3 + 1]; a[5] = t1d[r * 3 + 2];
        a[6] = 2.f * p0 - a[0]; a[7] = 2.f * p1 - a[1]; a[8] = 2.f * p2 - a[2];

        float2 pi[4], pc[4], po[4];
#pragma unroll
        for (int c = 0; c < 4; c++) {
            int u = 2 * lane + 64 * c;
            pi[c] = make_float2(sB[u], sB[u + 1]);
            pc[c] = make_float2(sB[256 + u], sB[256 + u + 1]);
            po[c] = make_float2(sB[512 + u], sB[512 + u + 1]);
        }
#pragma unroll
        for (int k = 0; k < 9; k++) {
            float ak = a[k];
            int kb = k * 384;
#pragma unroll
            for (int c = 0; c < 4; c++) {
                int h2i = lane + 32 * c;
                float2 wi = __half22float2(sW2[kb + h2i]);
                pi[c].x += ak * wi.x; pi[c].y += ak * wi.y;
                float2 wc2 = __half22float2(sW2[kb + 128 + h2i]);
                pc[c].x += ak * wc2.x; pc[c].y += ak * wc2.y;
                float2 wo = __half22float2(sW2[kb + 256 + h2i]);
                po[c].x += ak * wo.x; po[c].y += ak * wo.y;
            }
        }
#pragma unroll
        for (int c = 0; c < 4; c++) {
            int u = 2 * lane + 64 * c;
            float I0 = fsig(pi[c].x), T0 = ftanh(pc[c].x), C0 = I0 * T0;
            float O0 = fsig(po[c].x + wcO[u] * C0);
            float y0 = O0 * ftanh(C0); y0 = y0 > 0.f ? y0 : 0.1f * y0;
            float I1 = fsig(pi[c].y), T1 = ftanh(pc[c].y), C1 = I1 * T1;
            float O1 = fsig(po[c].y + wcO[u + 1] * C1);
            float y1 = O1 * ftanh(C1); y1 = y1 > 0.f ? y1 : 0.1f * y1;
            *reinterpret_cast<__half2*>(outA + (size_t)r * 256 + u) =
                __floats2half2_rn(y0, y1);
        }
    }
}

// ====================== SpMV (fp16 IO, unroll-4, single output) ============

template <int F, int CHEB2>
__global__ void k_spmv(const __half* __restrict__ X, const __half* __restrict__ X0,
                       __half* __restrict__ Y, int n, int npad) {
    const int TPR = F / 4;
    int tid = threadIdx.x;
    int row = blockIdx.x * (256 / TPR) + tid / TPR;
    int f = (tid % TPR) * 4;
    if (row >= npad) return;
    float a0 = 0.f, a1 = 0.f, a2 = 0.f, a3 = 0.f;
    if (row < n) {
        int j0 = g_roff[row], j1 = g_roff[row + 1];
        int j = j0;
        int jend = j0 + ((j1 - j0) & ~3);
        for (; j < jend; j += 4) {
            int2 e0 = g_edge[j], e1 = g_edge[j + 1];
            int2 e2 = g_edge[j + 2], e3 = g_edge[j + 3];
            float2 r0 = *reinterpret_cast<const float2*>(X + (size_t)e0.x * F + f);
            float2 r1 = *reinterpret_cast<const float2*>(X + (size_t)e1.x * F + f);
            float2 r2 = *reinterpret_cast<const float2*>(X + (size_t)e2.x * F + f);
            float2 r3 = *reinterpret_cast<const float2*>(X + (size_t)e3.x * F + f);
            float w0 = __int_as_float(e0.y), w1 = __int_as_float(e1.y);
            float w2 = __int_as_float(e2.y), w3 = __int_as_float(e3.y);
            {
                float2 f01 = __half22float2(*reinterpret_cast<__half2*>(&r0.x));
                float2 f23 = __half22float2(*reinterpret_cast<__half2*>(&r0.y));
                a0 += w0 * f01.x; a1 += w0 * f01.y; a2 += w0 * f23.x; a3 += w0 * f23.y;
            }
            {
                float2 f01 = __half22float2(*reinterpret_cast<__half2*>(&r1.x));
                float2 f23 = __half22float2(*reinterpret_cast<__half2*>(&r1.y));
                a0 += w1 * f01.x; a1 += w1 * f01.y; a2 += w1 * f23.x; a3 += w1 * f23.y;
            }
            {
                float2 f01 = __half22float2(*reinterpret_cast<__half2*>(&r2.x));
                float2 f23 = __half22float2(*reinterpret_cast<__half2*>(&r2.y));
                a0 += w2 * f01.x; a1 += w2 * f01.y; a2 += w2 * f23.x; a3 += w2 * f23.y;
            }
            {
                float2 f01 = __half22float2(*reinterpret_cast<__half2*>(&r3.x));
                float2 f23 = __half22float2(*reinterpret_cast<__half2*>(&r3.y));
                a0 += w3 * f01.x; a1 += w3 * f01.y; a2 += w3 * f23.x; a3 += w3 * f23.y;
            }
        }
        for (; j < j1; j++) {
            int2 e = g_edge[j];
            float w = __int_as_float(e.y);
            float2 raw = *reinterpret_cast<const float2*>(X + (size_t)e.x * F + f);
            float2 f01 = __half22float2(*reinterpret_cast<__half2*>(&raw.x));
            float2 f23 = __half22float2(*reinterpret_cast<__half2*>(&raw.y));
            a0 += w * f01.x; a1 += w * f01.y; a2 += w * f23.x; a3 += w * f23.y;
        }
        if (CHEB2) {
            float2 raw = *reinterpret_cast<const float2*>(X0 + (size_t)row * F + f);
            float2 f01 = __half22float2(*reinterpret_cast<__half2*>(&raw.x));
            float2 f23 = __half22float2(*reinterpret_cast<__half2*>(&raw.y));
            a0 = 2.f * a0 - f01.x; a1 = 2.f * a1 - f01.y;
            a2 = 2.f * a2 - f23.x; a3 = 2.f * a3 - f23.y;
        }
    }
    float2 packed;
    *reinterpret_cast<__half2*>(&packed.x) = __floats2half2_rn(a0, a1);
    *reinterpret_cast<__half2*>(&packed.y) = __floats2half2_rn(a2, a3);
    *reinterpret_cast<float2*>(Y + (size_t)row * F + f) = packed;
}

// ====================== mma.sync common helpers ============================

#define CP16(dst, src) \
    asm volatile("cp.async.ca.shared.global [%0], [%1], 16;\n" :: "r"(dst), "l"(src))
#define CP_COMMIT() asm volatile("cp.async.commit_group;\n" ::: "memory")
#define CP_WAIT1()  asm volatile("cp.async.wait_group 1;\n" ::: "memory")
#define CP_WAIT0()  asm volatile("cp.async.wait_group 0;\n" ::: "memory")

__device__ __forceinline__ uint32_t smem_u32(const void* p) {
    uint32_t a;
    asm("{ .reg .u64 t; cvta.to.shared.u64 t, %1; cvt.u32.u64 %0, t; }"
        : "=r"(a) : "l"(p));
    return a;
}

__device__ __forceinline__ void ldm_x4(uint32_t* r, uint32_t addr) {
    asm volatile("ldmatrix.sync.aligned.m8n8.x4.shared.b16 {%0,%1,%2,%3}, [%4];"
                 : "=r"(r[0]), "=r"(r[1]), "=r"(r[2]), "=r"(r[3]) : "r"(addr));
}

__device__ __forceinline__ void mma16816h(float* c, const uint32_t* a, const uint32_t* b) {
    asm volatile(
        "mma.sync.aligned.m16n8k16.row.col.f32.f16.f16.f32 "
        "{%0,%1,%2,%3}, {%4,%5,%6,%7}, {%8,%9}, {%0,%1,%2,%3};"
        : "+f"(c[0]), "+f"(c[1]), "+f"(c[2]), "+f"(c[3])
        : "r"(a[0]), "r"(a[1]), "r"(a[2]), "r"(a[3]), "r"(b[0]), "r"(b[1]));
}

// ====================== lin GEMM (fp16, lrelu, fp16 out) ===================
// stage layout (80B rows): A rows 0-127, B rows 128-191. Stage = 15360B.
#define GSTAGE 15360

__global__ __launch_bounds__(256, 2) void gemm_mma2(
    const __half* __restrict__ A, const __half* __restrict__ B,
    const float* __restrict__ bias, __half* __restrict__ C,
    int M, int Kp, int Nc) {
    extern __shared__ char smem[];
    const uint32_t s0 = smem_u32(smem);
    const int tid = threadIdx.x;
    const int wid = tid >> 5;
    const int lane = tid & 31;
    const int wm = wid & 3, wn = wid >> 2;
    const int bn = blockIdx.x << 6;
    const int bm = blockIdx.y << 7;

    float acc[2][4][4];
#pragma unroll
    for (int i = 0; i < 2; i++)
#pragma unroll
        for (int j = 0; j < 4; j++)
#pragma unroll
            for (int k = 0; k < 4; k++) acc[i][j][k] = 0.f;

#define LOAD_STAGE(stg, kc) do {                                             \
    uint32_t dstBase = s0 + (stg) * GSTAGE;                                  \
    _Pragma("unroll")                                                        \
    for (int u = tid; u < 768; u += 256) {                                   \
        uint32_t d; const char* g;                                           \
        if (u < 512) {                                                       \
            int row = u >> 2, seg = u & 3;                                   \
            d = dstBase + row * 80 + seg * 16;                               \
            g = (const char*)A + ((size_t)(bm + row) * Kp + (kc)) * 2        \
                + seg * 16;                                                  \
        } else {                                                             \
            int t = u - 512; int row = t >> 2, seg = t & 3;                  \
            d = dstBase + (128 + row) * 80 + seg * 16;                       \
            g = (const char*)B + ((size_t)(bn + row) * Kp + (kc)) * 2        \
                + seg * 16;                                                  \
        }                                                                    \
        CP16(d, g);                                                          \
    } } while (0)

    const int nK = Kp >> 5;
    LOAD_STAGE(0, 0);
    CP_COMMIT();
    if (nK > 1) { LOAD_STAGE(1, 32); CP_COMMIT(); }

    for (int kt = 0; kt < nK; kt++) {
        if (kt + 1 < nK) CP_WAIT1(); else CP_WAIT0();
        __syncthreads();
        if (kt + 2 < nK) {
            LOAD_STAGE((kt + 2) % 3, (kt + 2) << 5);
            CP_COMMIT();
        }
        uint32_t base = s0 + (kt % 3) * GSTAGE;
        uint32_t kb = (lane >> 4) * 16;
        uint32_t arow = wm * 32 + (lane & 15);
        uint32_t brow = 128 + wn * 32 + (lane & 15);
#pragma unroll
        for (int kk = 0; kk < 2; kk++) {
            uint32_t a[2][4];
#pragma unroll
            for (int mt = 0; mt < 2; mt++)
                ldm_x4(a[mt], base + (arow + mt * 16) * 80 + kk * 32 + kb);
            uint32_t b[4][2];
#pragma unroll
            for (int j = 0; j < 2; j++) {
                uint32_t r[4];
                ldm_x4(r, base + (brow + j * 16) * 80 + kk * 32 + kb);
                b[2 * j][0] = r[0]; b[2 * j][1] = r[2];
                b[2 * j + 1][0] = r[1]; b[2 * j + 1][1] = r[3];
            }
#pragma unroll
            for (int mt = 0; mt < 2; mt++)
#pragma unroll
                for (int nt = 0; nt < 4; nt++)
                    mma16816h(acc[mt][nt], a[mt], b[nt]);
        }
    }

    const int gid = lane >> 2, tig = lane & 3;
#pragma unroll
    for (int mt = 0; mt < 2; mt++) {
#pragma unroll
        for (int half = 0; half < 2; half++) {
            int row = bm + wm * 32 + mt * 16 + half * 8 + gid;
            bool valid = row < M;
#pragma unroll
            for (int nt = 0; nt < 4; nt++) {
                int col = bn + wn * 32 + nt * 8 + tig * 2;
                float v0 = 0.f, v1 = 0.f;
                if (valid) {
                    v0 = acc[mt][nt][2 * half + 0] + bias[col];
                    v1 = acc[mt][nt][2 * half + 1] + bias[col + 1];
                    v0 = v0 > 0.f ? v0 : 0.1f * v0;
                    v1 = v1 > 0.f ? v1 : 0.1f * v1;
                }
                // unconditional store: zero-pads rows [M, Npad)
                *reinterpret_cast<__half2*>(C + (size_t)row * Nc + col) =
                    __floats2half2_rn(v0, v1);
            }
        }
    }
}

// ====================== fused gate GEMM + gate eval ========================
// A operand = three F-wide buffers (T0, T1, T2), selected per 32-col k-chunk.
// stage: A 128 rows + B 3*64 rows, 80B padded = 25600B. 3 stages = 76800B.
#define GSTAGE_G 25600

__global__ __launch_bounds__(256) void gemm_gates(
    const __half* __restrict__ A0, const __half* __restrict__ A1,
    const __half* __restrict__ A2p, const __half* __restrict__ B,
    const float* __restrict__ bias, const float* __restrict__ wcO,
    __half* __restrict__ outY, int M, int F, int H) {
    extern __shared__ char smem[];
    const uint32_t s0 = smem_u32(smem);
    const int tid = threadIdx.x;
    const int wid = tid >> 5;
    const int lane = tid & 31;
    const int wm = wid & 3, wn = wid >> 2;
    const int bn = blockIdx.x << 6;
    const int bm = blockIdx.y << 7;
    const int Kp = 3 * F;

    float accI[2][4][4], accC[2][4][4], accO[2][4][4];
#pragma unroll
    for (int i = 0; i < 2; i++)
#pragma unroll
        for (int j = 0; j < 4; j++)
#pragma unroll
            for (int k = 0; k < 4; k++) {
                accI[i][j][k] = 0.f; accC[i][j][k] = 0.f; accO[i][j][k] = 0.f;
            }

#define LOAD_STAGE_G(stg, kc) do {                                           \
    uint32_t dstBase = s0 + (stg) * GSTAGE_G;                                \
    int _sec = (kc) / F;                                                     \
    int _off = (kc) - _sec * F;                                              \
    const char* _Ab = (const char*)(_sec == 0 ? A0 : (_sec == 1 ? A1 : A2p));\
    _Pragma("unroll")                                                        \
    for (int u = tid; u < 1280; u += 256) {                                  \
        uint32_t d; const char* g;                                           \
        if (u < 512) {                                                       \
            int row = u >> 2, seg = u & 3;                                   \
            d = dstBase + row * 80 + seg * 16;                               \
            g = _Ab + ((size_t)(bm + row) * F + _off) * 2 + seg * 16;        \
        } else {                                                             \
            int t = u - 512; int gate = t >> 8; int tt = t & 255;            \
            int row = tt >> 2, seg = tt & 3;                                 \
            d = dstBase + (128 + gate * 64 + row) * 80 + seg * 16;           \
            g = (const char*)B + ((size_t)(gate * H + bn + row) * Kp + (kc)) \
                * 2 + seg * 16;                                              \
        }                                                                    \
        CP16(d, g);                                                          \
    } } while (0)

    const int nK = Kp >> 5;
    LOAD_STAGE_G(0, 0);
    CP_COMMIT();
    if (nK > 1) { LOAD_STAGE_G(1, 32); CP_COMMIT(); }

    for (int kt = 0; kt < nK; kt++) {
        if (kt + 1 < nK) CP_WAIT1(); else CP_WAIT0();
        __syncthreads();
        if (kt + 2 < nK) {
            LOAD_STAGE_G((kt + 2) % 3, (kt + 2) << 5);
            CP_COMMIT();
        }
        uint32_t base = s0 + (kt % 3) * GSTAGE_G;
        uint32_t kb = (lane >> 4) * 16;
        uint32_t arow = wm * 32 + (lane & 15);
#pragma unroll
        for (int kk = 0; kk < 2; kk++) {
            uint32_t a[2][4];
#pragma unroll
            for (int mt = 0; mt < 2; mt++)
                ldm_x4(a[mt], base + (arow + mt * 16) * 80 + kk * 32 + kb);
#pragma unroll
            for (int gate = 0; gate < 3; gate++) {
                uint32_t brow = 128 + gate * 64 + wn * 32 + (lane & 15);
                uint32_t b[4][2];
#pragma unroll
                for (int j = 0; j < 2; j++) {
                    uint32_t r[4];
                    ldm_x4(r, base + (brow + j * 16) * 80 + kk * 32 + kb);
                    b[2 * j][0] = r[0]; b[2 * j][1] = r[2];
                    b[2 * j + 1][0] = r[1]; b[2 * j + 1][1] = r[3];
                }
                float (*acc)[4][4] = gate == 0 ? accI : (gate == 1 ? accC : accO);
#pragma unroll
                for (int mt = 0; mt < 2; mt++)
#pragma unroll
                    for (int nt = 0; nt < 4; nt++)
                        mma16816h(acc[mt][nt], a[mt], b[nt]);
            }
        }
    }

    const int gid = lane >> 2, tig = lane & 3;
#pragma unroll
    for (int mt = 0; mt < 2; mt++) {
#pragma unroll
        for (int half = 0; half < 2; half++) {
            int row = bm + wm * 32 + mt * 16 + half * 8 + gid;
            bool valid = row < M;
#pragma unroll
            for (int nt = 0; nt < 4; nt++) {
                int col = bn + wn * 32 + nt * 8 + tig * 2;
                float y0 = 0.f, y1 = 0.f;
                if (valid) {
                    float vI0 = accI[mt][nt][2 * half + 0] + bias[col];
                    float vI1 = accI[mt][nt][2 * half + 1] + bias[col + 1];
                    float vC0 = accC[mt][nt][2 * half + 0] + bias[H + col];
                    float vC1 = accC[mt][nt][2 * half + 1] + bias[H + col + 1];
                    float vO0 = accO[mt][nt][2 * half + 0] + bias[2 * H + col];
                    float vO1 = accO[mt][nt][2 * half + 1] + bias[2 * H + col + 1];
                    float I0 = fsig(vI0), T0 = ftanh(vC0), Cv0 = I0 * T0;
                    float O0 = fsig(vO0 + wcO[col] * Cv0);
                    y0 = O0 * ftanh(Cv0); y0 = y0 > 0.f ? y0 : 0.1f * y0;
                    float I1 = fsig(vI1), T1 = ftanh(vC1), Cv1 = I1 * T1;
                    float O1 = fsig(vO1 + wcO[col + 1] * Cv1);
                    y1 = O1 * ftanh(Cv1); y1 = y1 > 0.f ? y1 : 0.1f * y1;
                }
                *reinterpret_cast<__half2*>(outY + (size_t)row * H + col) =
                    __floats2half2_rn(y0, y1);
            }
        }
    }
}

// ====================== layer-3 tail: lin3 on fp16 y =======================

__global__ __launch_bounds__(256) void k_lin3h(
    const __half* __restrict__ Y, const float* __restrict__ W,
    const float* __restrict__ b, float* __restrict__ out, int n) {
    __shared__ float sW3[192];
    int tid = threadIdx.x;
    if (tid < 192) sW3[tid] = W[tid];
    __syncthreads();
    int lane = tid & 31, w = tid >> 5;
    for (int rr = 0; rr < 8; rr++) {
        int r = blockIdx.x * 64 + w * 8 + rr;
        if (r >= n) return;
        const __half* y = Y + (size_t)r * 64;
        float p0 = 0.f, p1 = 0.f, p2 = 0.f;
#pragma unroll
        for (int k = 0; k < 2; k++) {
            int u = lane + 32 * k;
            float yv = __half2float(y[u]);
            p0 += yv * sW3[u * 3]; p1 += yv * sW3[u * 3 + 1]; p2 += yv * sW3[u * 3 + 2];
        }
#pragma unroll
        for (int off = 16; off; off >>= 1) {
            p0 += __shfl_xor_sync(0xffffffffu, p0, off);
            p1 += __shfl_xor_sync(0xffffffffu, p1, off);
            p2 += __shfl_xor_sync(0xffffffffu, p2, off);
        }
        if (lane == 0) {
            out[r * 3] = p0 + b[0];
            out[r * 3 + 1] = p1 + b[1];
            out[r * 3 + 2] = p2 + b[2];
        }
    }
}

// ====================== host orchestration =================================

static inline int ceildiv(int a, int b) { return (a + b - 1) / b; }

extern "C" void kernel_launch(void* const* d_in, const int* in_sizes, int n_in,
                              void* d_out, int out_size) {
    const float* x = (const float*)d_in[0];
    const int* ei = (const int*)d_in[1];
    int N = in_sizes[0] / 3;
    int E = in_sizes[1] / 2;
    const int* src = ei;
    const int* dst = ei + E;
    int Npad = (N + 127) & ~127;
    int Mt = Npad / 128;

    const float* l1_Wx = (const float*)d_in[2];
    const float* l1_bx = (const float*)d_in[3];
    const float* l1_bh = (const float*)d_in[5];
    const float* l1_wc = (const float*)d_in[6];
    const float* l1_b  = (const float*)d_in[7];
    const float* l2_Wx = (const float*)d_in[8];
    const float* l2_bx = (const float*)d_in[9];
    const float* l2_bh = (const float*)d_in[11];
    const float* l2_wc = (const float*)d_in[12];
    const float* l2_b  = (const float*)d_in[13];
    const float* l3_Wx = (const float*)d_in[14];
    const float* l3_bx = (const float*)d_in[15];
    const float* l3_bh = (const float*)d_in[17];
    const float* l3_wc = (const float*)d_in[18];
    const float* l3_b  = (const float*)d_in[19];
    const float* lin1_W = (const float*)d_in[20];
    const float* lin1_b = (const float*)d_in[21];
    const float* lin2_W = (const float*)d_in[22];
    const float* lin2_b = (const float*)d_in[23];
    const float* lin3_W = (const float*)d_in[24];
    const float* lin3_b = (const float*)d_in[25];
    float* out = (float*)d_out;

    void* p;
    cudaGetSymbolAddress(&p, g_tmp);   int* tmp = (int*)p;
    cudaGetSymbolAddress(&p, g_xc);    float* xcf = (float*)p;
    __half* T1 = (__half*)xcf;
    cudaGetSymbolAddress(&p, g_h2);    __half* H2 = (__half*)p;
    cudaGetSymbolAddress(&p, g_t2buf); __half* T2 = (__half*)p;
    cudaGetSymbolAddress(&p, g_wbias); float* wb = (float*)p;
    cudaGetSymbolAddress(&p, g_bufB);  __half* bufB = (__half*)p;
    cudaGetSymbolAddress(&p, g_bbuf);  __half* bb = (__half*)p;

    cudaFuncSetAttribute(gemm_mma2, cudaFuncAttributeMaxDynamicSharedMemorySize,
                         3 * GSTAGE);
    cudaFuncSetAttribute(gemm_gates, cudaFuncAttributeMaxDynamicSharedMemorySize,
                         3 * GSTAGE_G);

    cudaStream_t s = 0;

    // ---- graph preprocessing ----
    cudaMemsetAsync(tmp, 0, 3 * MAXN * sizeof(int), s);
    k_degree<<<ceildiv(E, 256), 256, 0, s>>>(src, dst, E);
    k_scan<<<1, 1024, 0, s>>>(N);
    k_fill<<<ceildiv(E, 256), 256, 0, s>>>(src, dst, E);

    // ---- all weight/bias preprocessing in one kernel ----
    k_prep_all<<<ceildiv(E6, 256), 256, 0, s>>>(
        l1_Wx, l2_Wx, l3_Wx, lin1_W, lin2_W,
        l1_bx, l1_bh, l1_b, l2_bx, l2_bh, l2_b, l3_bx, l3_bh, l3_b);

    // ================= layer 1 (F=3, H=256) — fully fused ===================
    k_l1a<<<ceildiv(N, 256), 256, 0, s>>>(x, xcf, N);
    k_l1gates<<<ceildiv(Npad, 64), 256, 0, s>>>(x, xcf, l1_wc + 512, bufB, N, Npad);
    // lin1: [N,256]@[256,128] + lrelu -> H2 (T0 of layer 2, fp16, zero-padded)
    gemm_mma2<<<dim3(2, Mt), 256, 3 * GSTAGE, s>>>(
        bufB, bb + O_BL1, lin1_b, H2, N, 256, 128);

    // ================= layer 2 (F=128, H=128) =================
    k_spmv<128, 0><<<ceildiv(Npad, 8), 256, 0, s>>>(H2, nullptr, T1, N, Npad);
    k_spmv<128, 1><<<ceildiv(Npad, 8), 256, 0, s>>>(T1, H2, T2, N, Npad);
    // fused gate GEMM (A = {H2, T1, T2}) + gate eval -> bufB [Npad, 128]
    gemm_gates<<<dim3(2, Mt), 256, 3 * GSTAGE_G, s>>>(
        H2, T1, T2, bb + O_B2, wb + 768, l2_wc + 256, bufB, N, 128, 128);
    // lin2: [N,128]@[128,64] + lrelu -> H2 (T0 of layer 3, 64-wide)
    gemm_mma2<<<dim3(1, Mt), 256, 3 * GSTAGE, s>>>(
        bufB, bb + O_BL2, lin2_b, H2, N, 128, 64);

    // ================= layer 3 (F=64, H=64) =================
    k_spmv<64, 0><<<ceildiv(Npad, 16), 256, 0, s>>>(H2, nullptr, T1, N, Npad);
    k_spmv<64, 1><<<ceildiv(Npad, 16), 256, 0, s>>>(T1, H2, T2, N, Npad);
    gemm_gates<<<dim3(1, Mt), 256, 3 * GSTAGE_G, s>>>(
        H2, T1, T2, bb + O_B3, wb + 1152, l3_wc + 128, bufB, N, 64, 64);
    k_lin3h<<<ceildiv(N, 64), 256, 0, s>>>(bufB, lin3_W, lin3_b, out, N);
}

// round 15
// speedup vs baseline: 1.1130x; 1.0069x over previous
#include <cuda_runtime.h>
#include <cuda_fp16.h>
#include <math.h>
#include <stdint.h>

// ---------------- problem-size caps (fixed by setup_inputs) ----------------
#define MAXN 50000
#define NPADMAX 50048   // MAXN rounded up to 128

// ---------------- device scratch (no allocation allowed) -------------------
__device__ int   g_tmp[3 * MAXN];    // deg | cnt | cur (one memset)
__device__ int   g_roff[MAXN + 1];
__device__ int2  g_edge[800000];     // packed (src, weight-bits)
__device__ float g_xc[(size_t)MAXN * 384];     // T1 buffer (fp16 view) / l1 fp32
__device__ float g_h2[(size_t)MAXN * 128];     // T0 buffer (fp16 view)
__device__ float g_wbias[1344];                // combined gate biases (l1|l2|l3)
__device__ float g_w1t[9 * 768];               // layer1 gate weights transposed fp32
__device__ __align__(256) __half g_t2buf[(size_t)NPADMAX * 128]; // T2 buffer
__device__ __align__(256) __half g_bufB[(size_t)NPADMAX * 256];  // lin A / gate-out
__device__ __align__(256) __half g_bbuf[262144];                 // weights fp16

// weight buffer element offsets (rows x Kp, single fp16)
#define O_B2  24576    // l2 gate: 384 x 384
#define O_B3  172032   // l3 gate: 192 x 192
#define O_BL1 208896   // lin1: 128 x 256
#define O_BL2 241664   // lin2: 64 x 128

// ====================== graph preprocessing ================================

__global__ void k_degree(const int* __restrict__ src, const int* __restrict__ dst, int E) {
    int e = blockIdx.x * blockDim.x + threadIdx.x;
    if (e >= E) return;
    atomicAdd(&g_tmp[src[e]], 1);            // deg
    atomicAdd(&g_tmp[MAXN + dst[e]], 1);     // cnt
}

__global__ void k_scan(int n) {
    __shared__ int ssum[1024];
    int tid = threadIdx.x;
    const int T = 1024;
    int chunk = (n + T - 1) / T;
    int beg = tid * chunk;
    int end = beg + chunk; if (end > n) end = n;
    int s = 0;
    for (int i = beg; i < end; i++) s += g_tmp[MAXN + i];
    ssum[tid] = s;
    __syncthreads();
    for (int off = 1; off < T; off <<= 1) {
        int v = (tid >= off) ? ssum[tid - off] : 0;
        __syncthreads();
        ssum[tid] += v;
        __syncthreads();
    }
    int run = (tid > 0) ? ssum[tid - 1] : 0;
    for (int i = beg; i < end; i++) { g_roff[i] = run; run += g_tmp[MAXN + i]; }
    if (tid == T - 1) g_roff[n] = ssum[T - 1];
}

__global__ void k_fill(const int* __restrict__ src, const int* __restrict__ dst, int E) {
    int e = blockIdx.x * blockDim.x + threadIdx.x;
    if (e >= E) return;
    int s = src[e], d = dst[e];
    int pos = g_roff[d] + atomicAdd(&g_tmp[2 * MAXN + d], 1);
    int ds = g_tmp[s], dd = g_tmp[d];
    float is = ds > 0 ? rsqrtf((float)ds) : 0.0f;
    float id = dd > 0 ? rsqrtf((float)dd) : 0.0f;
    g_edge[pos] = make_int2(s, __float_as_int(-is * id));
}

// ====================== merged weight/bias preprocessing ===================

__device__ __forceinline__ void prep_gateB(const float* __restrict__ Wx, int F, int H,
                                           int Kp, int nrow, int kk,
                                           __half* __restrict__ dst) {
    int gp = nrow / H, o = nrow % H;
    int gate = (gp == 0) ? 0 : (gp + 1);   // gates {0,2,3}
    float w = 0.0f;
    if (kk < 3 * F) {
        int kc = kk / F, f = kk % F;
        w = Wx[(((size_t)gate * 3 + kc) * F + f) * H + o];
    }
    dst[(size_t)nrow * Kp + kk] = __float2half_rn(w);
}

__device__ __forceinline__ void prep_linB(const float* __restrict__ W, int Hout,
                                          int Kp, int nrow, int kk,
                                          __half* __restrict__ dst) {
    dst[(size_t)nrow * Kp + kk] = __float2half_rn(W[(size_t)kk * Hout + nrow]);
}

#define E1 24576     // 768*32 (layer1 -> transposed fp32 table)
#define E2 172032    // +384*384
#define E3 208896    // +192*192
#define E4 241664    // +128*256
#define E5 249856    // +64*128
#define E6 251200    // +1344 biases

__global__ void k_prep_all(
    const float* __restrict__ w1, const float* __restrict__ w2, const float* __restrict__ w3,
    const float* __restrict__ wl1, const float* __restrict__ wl2,
    const float* __restrict__ bx1, const float* __restrict__ bh1, const float* __restrict__ b1,
    const float* __restrict__ bx2, const float* __restrict__ bh2, const float* __restrict__ b2,
    const float* __restrict__ bx3, const float* __restrict__ bh3, const float* __restrict__ b3) {
    int idx = blockIdx.x * blockDim.x + threadIdx.x;
    if (idx >= E6) return;
    if (idx < E1) {
        int nrow = idx / 32, kk = idx % 32;
        if (kk < 9) {
            int gp = nrow / 256, o = nrow % 256;
            int gate = (gp == 0) ? 0 : (gp + 1);
            int kc = kk / 3, f = kk % 3;
            g_w1t[kk * 768 + nrow] = w1[(((size_t)gate * 3 + kc) * 3 + f) * 256 + o];
        }
    } else if (idx < E2) {
        int t = idx - E1;
        prep_gateB(w2, 128, 128, 384, t / 384, t % 384, g_bbuf + O_B2);
    } else if (idx < E3) {
        int t = idx - E2;
        prep_gateB(w3, 64, 64, 192, t / 192, t % 192, g_bbuf + O_B3);
    } else if (idx < E4) {
        int t = idx - E3;
        prep_linB(wl1, 128, 256, t / 256, t % 256, g_bbuf + O_BL1);
    } else if (idx < E5) {
        int t = idx - E4;
        prep_linB(wl2, 64, 128, t / 128, t % 128, g_bbuf + O_BL2);
    } else {
        int t = idx - E5;
        const float *bx, *bh, *bb; int H, base;
        if (t < 768)       { bx = bx1; bh = bh1; bb = b1; H = 256; base = 0; }
        else if (t < 1152) { bx = bx2; bh = bh2; bb = b2; H = 128; base = 768; t -= 768; }
        else               { bx = bx3; bh = bh3; bb = b3; H = 64;  base = 1152; t -= 1152; }
        int gp = t / H, o = t % H;
        int gate = (gp == 0) ? 0 : (gp + 1);
        g_wbias[base + t] = bx[gate * H + o] + bh[gate * H + o] + bb[gate * H + o];
    }
}

// ====================== fast transcendentals (HW tanh) =====================

__device__ __forceinline__ float ftanh(float x) {
    float y;
    asm("tanh.approx.f32 %0, %1;" : "=f"(y) : "f"(x));
    return y;
}
__device__ __forceinline__ float fsig(float x) {
    return fmaf(ftanh(0.5f * x), 0.5f, 0.5f);
}

// ====================== layer-1: T1 dense pass (unroll-4) ==================

__global__ void k_l1a(const float* __restrict__ x, float* __restrict__ t1d, int n) {
    int row = blockIdx.x * blockDim.x + threadIdx.x;
    if (row >= n) return;
    float t1[3] = {0, 0, 0};
    int j0 = g_roff[row], j1 = g_roff[row + 1];
    int j = j0;
    int jend = j0 + ((j1 - j0) & ~3);
    for (; j < jend; j += 4) {
        int2 e0 = g_edge[j], e1 = g_edge[j + 1], e2 = g_edge[j + 2], e3 = g_edge[j + 3];
        const float* x0 = x + (size_t)e0.x * 3;
        const float* x1 = x + (size_t)e1.x * 3;
        const float* x2 = x + (size_t)e2.x * 3;
        const float* x3 = x + (size_t)e3.x * 3;
        float v00 = x0[0], v01 = x0[1], v02 = x0[2];
        float v10 = x1[0], v11 = x1[1], v12 = x1[2];
        float v20 = x2[0], v21 = x2[1], v22 = x2[2];
        float v30 = x3[0], v31 = x3[1], v32 = x3[2];
        float w0 = __int_as_float(e0.y), w1 = __int_as_float(e1.y);
        float w2 = __int_as_float(e2.y), w3 = __int_as_float(e3.y);
        t1[0] += w0 * v00 + w1 * v10 + w2 * v20 + w3 * v30;
        t1[1] += w0 * v01 + w1 * v11 + w2 * v21 + w3 * v31;
        t1[2] += w0 * v02 + w1 * v12 + w2 * v22 + w3 * v32;
    }
    for (; j < j1; j++) {
        int2 e = g_edge[j];
        float w = __int_as_float(e.y);
        const float* xr = x + (size_t)e.x * 3;
        t1[0] += w * xr[0]; t1[1] += w * xr[1]; t1[2] += w * xr[2];
    }
    t1d[row * 3] = t1[0]; t1d[row * 3 + 1] = t1[1]; t1d[row * 3 + 2] = t1[2];
}

// ====================== layer-1 fused: T2 gather + gates -> bufB ===========

__global__ __launch_bounds__(256) void k_l1gates(
    const float* __restrict__ x, const float* __restrict__ t1d,
    const float* __restrict__ wcO, __half* __restrict__ outA, int n, int npad) {
    __shared__ __half sW[9 * 768];
    __shared__ float sB[768];
    int tid = threadIdx.x;
    for (int i = tid; i < 9 * 768; i += 256) sW[i] = __float2half_rn(g_w1t[i]);
    for (int i = tid; i < 768; i += 256) sB[i] = g_wbias[i];
    __syncthreads();
    const __half2* sW2 = reinterpret_cast<const __half2*>(sW);
    int lane = tid & 31, w = tid >> 5;

    for (int rr = 0; rr < 8; rr++) {
        int r = blockIdx.x * 64 + w * 8 + rr;
        if (r >= npad) return;
        if (r >= n) {
#pragma unroll
            for (int c = 0; c < 4; c++)
                *reinterpret_cast<__half2*>(outA + (size_t)r * 256 + 2 * lane + 64 * c) =
                    __floats2half2_rn(0.f, 0.f);
            continue;
        }
        float p0 = 0.f, p1 = 0.f, p2 = 0.f;
        int j0 = g_roff[r], j1 = g_roff[r + 1];
        for (int j = j0 + lane; j < j1; j += 32) {
            int2 e = g_edge[j];
            float wgt = __int_as_float(e.y);
            const float* tr = t1d + (size_t)e.x * 3;
            p0 += wgt * tr[0]; p1 += wgt * tr[1]; p2 += wgt * tr[2];
        }
#pragma unroll
        for (int off = 16; off; off >>= 1) {
            p0 += __shfl_xor_sync(0xffffffffu, p0, off);
            p1 += __shfl_xor_sync(0xffffffffu, p1, off);
            p2 += __shfl_xor_sync(0xffffffffu, p2, off);
        }
        float a[9];
        a[0] = x[r * 3]; a[1] = x[r * 3 + 1]; a[2] = x[r * 3 + 2];
        a[3] = t1d[r * 3]; a[4] = t1d[r * 3 + 1]; a[5] = t1d[r * 3 + 2];
        a[6] = 2.f * p0 - a[0]; a[7] = 2.f * p1 - a[1]; a[8] = 2.f * p2 - a[2];

        float2 pi[4], pc[4], po[4];
#pragma unroll
        for (int c = 0; c < 4; c++) {
            int u = 2 * lane + 64 * c;
            pi[c] = make_float2(sB[u], sB[u + 1]);
            pc[c] = make_float2(sB[256 + u], sB[256 + u + 1]);
            po[c] = make_float2(sB[512 + u], sB[512 + u + 1]);
        }
#pragma unroll
        for (int k = 0; k < 9; k++) {
            float ak = a[k];
            int kb = k * 384;
#pragma unroll
            for (int c = 0; c < 4; c++) {
                int h2i = lane + 32 * c;
                float2 wi = __half22float2(sW2[kb + h2i]);
                pi[c].x += ak * wi.x; pi[c].y += ak * wi.y;
                float2 wc2 = __half22float2(sW2[kb + 128 + h2i]);
                pc[c].x += ak * wc2.x; pc[c].y += ak * wc2.y;
                float2 wo = __half22float2(sW2[kb + 256 + h2i]);
                po[c].x += ak * wo.x; po[c].y += ak * wo.y;
            }
        }
#pragma unroll
        for (int c = 0; c < 4; c++) {
            int u = 2 * lane + 64 * c;
            float I0 = fsig(pi[c].x), T0 = ftanh(pc[c].x), C0 = I0 * T0;
            float O0 = fsig(po[c].x + wcO[u] * C0);
            float y0 = O0 * ftanh(C0); y0 = y0 > 0.f ? y0 : 0.1f * y0;
            float I1 = fsig(pi[c].y), T1 = ftanh(pc[c].y), C1 = I1 * T1;
            float O1 = fsig(po[c].y + wcO[u + 1] * C1);
            float y1 = O1 * ftanh(C1); y1 = y1 > 0.f ? y1 : 0.1f * y1;
            *reinterpret_cast<__half2*>(outA + (size_t)r * 256 + u) =
                __floats2half2_rn(y0, y1);
        }
    }
}

// ====================== SpMV (fp16 IO, float4 gathers, unroll-2) ===========

template <int F, int CHEB2>
__global__ void k_spmv(const __half* __restrict__ X, const __half* __restrict__ X0,
                       __half* __restrict__ Y, int n, int npad) {
    const int TPR = F / 8;   // 8 halves per thread
    int tid = threadIdx.x;
    int row = blockIdx.x * (256 / TPR) + tid / TPR;
    int f = (tid % TPR) * 8;
    if (row >= npad) return;
    float a[8] = {0, 0, 0, 0, 0, 0, 0, 0};
    if (row < n) {
        int j0 = g_roff[row], j1 = g_roff[row + 1];
        int j = j0;
        int jend = j0 + ((j1 - j0) & ~1);
        for (; j < jend; j += 2) {
            int2 e0 = g_edge[j], e1 = g_edge[j + 1];
            float4 r0 = *reinterpret_cast<const float4*>(X + (size_t)e0.x * F + f);
            float4 r1 = *reinterpret_cast<const float4*>(X + (size_t)e1.x * F + f);
            float w0 = __int_as_float(e0.y), w1 = __int_as_float(e1.y);
            const __half2* h0 = reinterpret_cast<const __half2*>(&r0);
            const __half2* h1 = reinterpret_cast<const __half2*>(&r1);
#pragma unroll
            for (int q = 0; q < 4; q++) {
                float2 f0 = __half22float2(h0[q]);
                float2 f1 = __half22float2(h1[q]);
                a[2 * q] += w0 * f0.x + w1 * f1.x;
                a[2 * q + 1] += w0 * f0.y + w1 * f1.y;
            }
        }
        for (; j < j1; j++) {
            int2 e = g_edge[j];
            float w = __int_as_float(e.y);
            float4 raw = *reinterpret_cast<const float4*>(X + (size_t)e.x * F + f);
            const __half2* h = reinterpret_cast<const __half2*>(&raw);
#pragma unroll
            for (int q = 0; q < 4; q++) {
                float2 fv = __half22float2(h[q]);
                a[2 * q] += w * fv.x;
                a[2 * q + 1] += w * fv.y;
            }
        }
        if (CHEB2) {
            float4 raw = *reinterpret_cast<const float4*>(X0 + (size_t)row * F + f);
            const __half2* h = reinterpret_cast<const __half2*>(&raw);
#pragma unroll
            for (int q = 0; q < 4; q++) {
                float2 fv = __half22float2(h[q]);
                a[2 * q] = 2.f * a[2 * q] - fv.x;
                a[2 * q + 1] = 2.f * a[2 * q + 1] - fv.y;
            }
        }
    }
    float4 packed;
    __half2* ph = reinterpret_cast<__half2*>(&packed);
#pragma unroll
    for (int q = 0; q < 4; q++)
        ph[q] = __floats2half2_rn(a[2 * q], a[2 * q + 1]);
    *reinterpret_cast<float4*>(Y + (size_t)row * F + f) = packed;
}

// ====================== mma.sync common helpers ============================

#define CP16(dst, src) \
    asm volatile("cp.async.ca.shared.global [%0], [%1], 16;\n" :: "r"(dst), "l"(src))
#define CP_COMMIT() asm volatile("cp.async.commit_group;\n" ::: "memory")
#define CP_WAIT1()  asm volatile("cp.async.wait_group 1;\n" ::: "memory")
#define CP_WAIT0()  asm volatile("cp.async.wait_group 0;\n" ::: "memory")

__device__ __forceinline__ uint32_t smem_u32(const void* p) {
    uint32_t a;
    asm("{ .reg .u64 t; cvta.to.shared.u64 t, %1; cvt.u32.u64 %0, t; }"
        : "=r"(a) : "l"(p));
    return a;
}

__device__ __forceinline__ void ldm_x4(uint32_t* r, uint32_t addr) {
    asm volatile("ldmatrix.sync.aligned.m8n8.x4.shared.b16 {%0,%1,%2,%3}, [%4];"
                 : "=r"(r[0]), "=r"(r[1]), "=r"(r[2]), "=r"(r[3]) : "r"(addr));
}

__device__ __forceinline__ void mma16816h(float* c, const uint32_t* a, const uint32_t* b) {
    asm volatile(
        "mma.sync.aligned.m16n8k16.row.col.f32.f16.f16.f32 "
        "{%0,%1,%2,%3}, {%4,%5,%6,%7}, {%8,%9}, {%0,%1,%2,%3};"
        : "+f"(c[0]), "+f"(c[1]), "+f"(c[2]), "+f"(c[3])
        : "r"(a[0]), "r"(a[1]), "r"(a[2]), "r"(a[3]), "r"(b[0]), "r"(b[1]));
}

// ====================== lin GEMM (fp16, lrelu, fp16 out) ===================
// stage layout (80B rows): A rows 0-127, B rows 128-191. Stage = 15360B.
#define GSTAGE 15360

__global__ __launch_bounds__(256, 2) void gemm_mma2(
    const __half* __restrict__ A, const __half* __restrict__ B,
    const float* __restrict__ bias, __half* __restrict__ C,
    int M, int Kp, int Nc) {
    extern __shared__ char smem[];
    const uint32_t s0 = smem_u32(smem);
    const int tid = threadIdx.x;
    const int wid = tid >> 5;
    const int lane = tid & 31;
    const int wm = wid & 3, wn = wid >> 2;
    const int bn = blockIdx.x << 6;
    const int bm = blockIdx.y << 7;

    float acc[2][4][4];
#pragma unroll
    for (int i = 0; i < 2; i++)
#pragma unroll
        for (int j = 0; j < 4; j++)
#pragma unroll
            for (int k = 0; k < 4; k++) acc[i][j][k] = 0.f;

#define LOAD_STAGE(stg, kc) do {                                             \
    uint32_t dstBase = s0 + (stg) * GSTAGE;                                  \
    _Pragma("unroll")                                                        \
    for (int u = tid; u < 768; u += 256) {                                   \
        uint32_t d; const char* g;                                           \
        if (u < 512) {                                                       \
            int row = u >> 2, seg = u & 3;                                   \
            d = dstBase + row * 80 + seg * 16;                               \
            g = (const char*)A + ((size_t)(bm + row) * Kp + (kc)) * 2        \
                + seg * 16;                                                  \
        } else {                                                             \
            int t = u - 512; int row = t >> 2, seg = t & 3;                  \
            d = dstBase + (128 + row) * 80 + seg * 16;                       \
            g = (const char*)B + ((size_t)(bn + row) * Kp + (kc)) * 2        \
                + seg * 16;                                                  \
        }                                                                    \
        CP16(d, g);                                                          \
    } } while (0)

    const int nK = Kp >> 5;
    LOAD_STAGE(0, 0);
    CP_COMMIT();
    if (nK > 1) { LOAD_STAGE(1, 32); CP_COMMIT(); }

    for (int kt = 0; kt < nK; kt++) {
        if (kt + 1 < nK) CP_WAIT1(); else CP_WAIT0();
        __syncthreads();
        if (kt + 2 < nK) {
            LOAD_STAGE((kt + 2) % 3, (kt + 2) << 5);
            CP_COMMIT();
        }
        uint32_t base = s0 + (kt % 3) * GSTAGE;
        uint32_t kb = (lane >> 4) * 16;
        uint32_t arow = wm * 32 + (lane & 15);
        uint32_t brow = 128 + wn * 32 + (lane & 15);
#pragma unroll
        for (int kk = 0; kk < 2; kk++) {
            uint32_t a[2][4];
#pragma unroll
            for (int mt = 0; mt < 2; mt++)
                ldm_x4(a[mt], base + (arow + mt * 16) * 80 + kk * 32 + kb);
            uint32_t b[4][2];
#pragma unroll
            for (int j = 0; j < 2; j++) {
                uint32_t r[4];
                ldm_x4(r, base + (brow + j * 16) * 80 + kk * 32 + kb);
                b[2 * j][0] = r[0]; b[2 * j][1] = r[2];
                b[2 * j + 1][0] = r[1]; b[2 * j + 1][1] = r[3];
            }
#pragma unroll
            for (int mt = 0; mt < 2; mt++)
#pragma unroll
                for (int nt = 0; nt < 4; nt++)
                    mma16816h(acc[mt][nt], a[mt], b[nt]);
        }
    }

    const int gid = lane >> 2, tig = lane & 3;
#pragma unroll
    for (int mt = 0; mt < 2; mt++) {
#pragma unroll
        for (int half = 0; half < 2; half++) {
            int row = bm + wm * 32 + mt * 16 + half * 8 + gid;
            bool valid = row < M;
#pragma unroll
            for (int nt = 0; nt < 4; nt++) {
                int col = bn + wn * 32 + nt * 8 + tig * 2;
                float v0 = 0.f, v1 = 0.f;
                if (valid) {
                    v0 = acc[mt][nt][2 * half + 0] + bias[col];
                    v1 = acc[mt][nt][2 * half + 1] + bias[col + 1];
                    v0 = v0 > 0.f ? v0 : 0.1f * v0;
                    v1 = v1 > 0.f ? v1 : 0.1f * v1;
                }
                // unconditional store: zero-pads rows [M, Npad)
                *reinterpret_cast<__half2*>(C + (size_t)row * Nc + col) =
                    __floats2half2_rn(v0, v1);
            }
        }
    }
}

// ====================== fused gate GEMM + gate eval (+opt lin3) ============
// A operand = three F-wide buffers (T0, T1, T2), selected per 32-col k-chunk.
// If W3 != nullptr (requires H==64, gridDim.x==1): fuse the final [64,3]
// projection via smem and write fp32 out directly (y never hits gmem).
// stage: A 128 rows + B 3*64 rows, 80B padded = 25600B. 3 stages = 76800B.
#define GSTAGE_G 25600

__global__ __launch_bounds__(256) void gemm_gates(
    const __half* __restrict__ A0, const __half* __restrict__ A1,
    const __half* __restrict__ A2p, const __half* __restrict__ B,
    const float* __restrict__ bias, const float* __restrict__ wcO,
    __half* __restrict__ outY, int M, int F, int H,
    const float* __restrict__ W3, const float* __restrict__ b3,
    float* __restrict__ outF) {
    extern __shared__ char smem[];
    __shared__ float sW3[192];
    const uint32_t s0 = smem_u32(smem);
    const int tid = threadIdx.x;
    const int wid = tid >> 5;
    const int lane = tid & 31;
    const int wm = wid & 3, wn = wid >> 2;
    const int bn = blockIdx.x << 6;
    const int bm = blockIdx.y << 7;
    const int Kp = 3 * F;

    if (W3 && tid < 192) sW3[tid] = W3[tid];

    float accI[2][4][4], accC[2][4][4], accO[2][4][4];
#pragma unroll
    for (int i = 0; i < 2; i++)
#pragma unroll
        for (int j = 0; j < 4; j++)
#pragma unroll
            for (int k = 0; k < 4; k++) {
                accI[i][j][k] = 0.f; accC[i][j][k] = 0.f; accO[i][j][k] = 0.f;
            }

#define LOAD_STAGE_G(stg, kc) do {                                           \
    uint32_t dstBase = s0 + (stg) * GSTAGE_G;                                \
    int _sec = (kc) / F;                                                     \
    int _off = (kc) - _sec * F;                                              \
    const char* _Ab = (const char*)(_sec == 0 ? A0 : (_sec == 1 ? A1 : A2p));\
    _Pragma("unroll")                                                        \
    for (int u = tid; u < 1280; u += 256) {                                  \
        uint32_t d; const char* g;                                           \
        if (u < 512) {                                                       \
            int row = u >> 2, seg = u & 3;                                   \
            d = dstBase + row * 80 + seg * 16;                               \
            g = _Ab + ((size_t)(bm + row) * F + _off) * 2 + seg * 16;        \
        } else {                                                             \
            int t = u - 512; int gate = t >> 8; int tt = t & 255;            \
            int row = tt >> 2, seg = tt & 3;                                 \
            d = dstBase + (128 + gate * 64 + row) * 80 + seg * 16;           \
            g = (const char*)B + ((size_t)(gate * H + bn + row) * Kp + (kc)) \
                * 2 + seg * 16;                                              \
        }                                                                    \
        CP16(d, g);                                                          \
    } } while (0)

    const int nK = Kp >> 5;
    LOAD_STAGE_G(0, 0);
    CP_COMMIT();
    if (nK > 1) { LOAD_STAGE_G(1, 32); CP_COMMIT(); }

    for (int kt = 0; kt < nK; kt++) {
        if (kt + 1 < nK) CP_WAIT1(); else CP_WAIT0();
        __syncthreads();
        if (kt + 2 < nK) {
            LOAD_STAGE_G((kt + 2) % 3, (kt + 2) << 5);
            CP_COMMIT();
        }
        uint32_t base = s0 + (kt % 3) * GSTAGE_G;
        uint32_t kb = (lane >> 4) * 16;
        uint32_t arow = wm * 32 + (lane & 15);
#pragma unroll
        for (int kk = 0; kk < 2; kk++) {
            uint32_t a[2][4];
#pragma unroll
            for (int mt = 0; mt < 2; mt++)
                ldm_x4(a[mt], base + (arow + mt * 16) * 80 + kk * 32 + kb);
#pragma unroll
            for (int gate = 0; gate < 3; gate++) {
                uint32_t brow = 128 + gate * 64 + wn * 32 + (lane & 15);
                uint32_t b[4][2];
#pragma unroll
                for (int j = 0; j < 2; j++) {
                    uint32_t r[4];
                    ldm_x4(r, base + (brow + j * 16) * 80 + kk * 32 + kb);
                    b[2 * j][0] = r[0]; b[2 * j][1] = r[2];
                    b[2 * j + 1][0] = r[1]; b[2 * j + 1][1] = r[3];
                }
                float (*acc)[4][4] = gate == 0 ? accI : (gate == 1 ? accC : accO);
#pragma unroll
                for (int mt = 0; mt < 2; mt++)
#pragma unroll
                    for (int nt = 0; nt < 4; nt++)
                        mma16816h(acc[mt][nt], a[mt], b[nt]);
            }
        }
    }

    const int gid = lane >> 2, tig = lane & 3;
    __half2* sy = reinterpret_cast<__half2*>(smem);   // [128][33] half2 units
    if (W3) __syncthreads();   // ensure all warps finished reading stages

#pragma unroll
    for (int mt = 0; mt < 2; mt++) {
#pragma unroll
        for (int half = 0; half < 2; half++) {
            int row = bm + wm * 32 + mt * 16 + half * 8 + gid;
            bool valid = row < M;
#pragma unroll
            for (int nt = 0; nt < 4; nt++) {
                int col = bn + wn * 32 + nt * 8 + tig * 2;
                float y0 = 0.f, y1 = 0.f;
                if (valid) {
                    float vI0 = accI[mt][nt][2 * half + 0] + bias[col];
                    float vI1 = accI[mt][nt][2 * half + 1] + bias[col + 1];
                    float vC0 = accC[mt][nt][2 * half + 0] + bias[H + col];
                    float vC1 = accC[mt][nt][2 * half + 1] + bias[H + col + 1];
                    float vO0 = accO[mt][nt][2 * half + 0] + bias[2 * H + col];
                    float vO1 = accO[mt][nt][2 * half + 1] + bias[2 * H + col + 1];
                    float I0 = fsig(vI0), T0 = ftanh(vC0), Cv0 = I0 * T0;
                    float O0 = fsig(vO0 + wcO[col] * Cv0);
                    y0 = O0 * ftanh(Cv0); y0 = y0 > 0.f ? y0 : 0.1f * y0;
                    float I1 = fsig(vI1), T1 = ftanh(vC1), Cv1 = I1 * T1;
                    float O1 = fsig(vO1 + wcO[col + 1] * Cv1);
                    y1 = O1 * ftanh(Cv1); y1 = y1 > 0.f ? y1 : 0.1f * y1;
                }
                if (W3) {
                    int rl = wm * 32 + mt * 16 + half * 8 + gid;
                    sy[rl * 33 + (col >> 1)] = __floats2half2_rn(y0, y1);
                } else {
                    *reinterpret_cast<__half2*>(outY + (size_t)row * H + col) =
                        __floats2half2_rn(y0, y1);
                }
            }
        }
    }

    if (W3) {
        __syncthreads();
        // each warp: 16 rows; lane covers half2 unit = 2 columns
        for (int rr = 0; rr < 16; rr++) {
            int rl = wid * 16 + rr;
            int r = bm + rl;
            if (r >= M) break;
            float2 fv = __half22float2(sy[rl * 33 + lane]);
            int u = lane * 2;
            float p0 = fv.x * sW3[u * 3]     + fv.y * sW3[(u + 1) * 3];
            float p1 = fv.x * sW3[u * 3 + 1] + fv.y * sW3[(u + 1) * 3 + 1];
            float p2 = fv.x * sW3[u * 3 + 2] + fv.y * sW3[(u + 1) * 3 + 2];
#pragma unroll
            for (int off = 16; off; off >>= 1) {
                p0 += __shfl_xor_sync(0xffffffffu, p0, off);
                p1 += __shfl_xor_sync(0xffffffffu, p1, off);
                p2 += __shfl_xor_sync(0xffffffffu, p2, off);
            }
            if (lane == 0) {
                outF[r * 3] = p0 + b3[0];
                outF[r * 3 + 1] = p1 + b3[1];
                outF[r * 3 + 2] = p2 + b3[2];
            }
        }
    }
}

// ====================== host orchestration =================================

static inline int ceildiv(int a, int b) { return (a + b - 1) / b; }

extern "C" void kernel_launch(void* const* d_in, const int* in_sizes, int n_in,
                              void* d_out, int out_size) {
    const float* x = (const float*)d_in[0];
    const int* ei = (const int*)d_in[1];
    int N = in_sizes[0] / 3;
    int E = in_sizes[1] / 2;
    const int* src = ei;
    const int* dst = ei + E;
    int Npad = (N + 127) & ~127;
    int Mt = Npad / 128;

    const float* l1_Wx = (const float*)d_in[2];
    const float* l1_bx = (const float*)d_in[3];
    const float* l1_bh = (const float*)d_in[5];
    const float* l1_wc = (const float*)d_in[6];
    const float* l1_b  = (const float*)d_in[7];
    const float* l2_Wx = (const float*)d_in[8];
    const float* l2_bx = (const float*)d_in[9];
    const float* l2_bh = (const float*)d_in[11];
    const float* l2_wc = (const float*)d_in[12];
    const float* l2_b  = (const float*)d_in[13];
    const float* l3_Wx = (const float*)d_in[14];
    const float* l3_bx = (const float*)d_in[15];
    const float* l3_bh = (const float*)d_in[17];
    const float* l3_wc = (const float*)d_in[18];
    const float* l3_b  = (const float*)d_in[19];
    const float* lin1_W = (const float*)d_in[20];
    const float* lin1_b = (const float*)d_in[21];
    const float* lin2_W = (const float*)d_in[22];
    const float* lin2_b = (const float*)d_in[23];
    const float* lin3_W = (const float*)d_in[24];
    const float* lin3_b = (const float*)d_in[25];
    float* out = (float*)d_out;

    void* p;
    cudaGetSymbolAddress(&p, g_tmp);   int* tmp = (int*)p;
    cudaGetSymbolAddress(&p, g_xc);    float* xcf = (float*)p;
    __half* T1 = (__half*)xcf;
    cudaGetSymbolAddress(&p, g_h2);    __half* H2 = (__half*)p;
    cudaGetSymbolAddress(&p, g_t2buf); __half* T2 = (__half*)p;
    cudaGetSymbolAddress(&p, g_wbias); float* wb = (float*)p;
    cudaGetSymbolAddress(&p, g_bufB);  __half* bufB = (__half*)p;
    cudaGetSymbolAddress(&p, g_bbuf);  __half* bb = (__half*)p;

    cudaFuncSetAttribute(gemm_mma2, cudaFuncAttributeMaxDynamicSharedMemorySize,
                         3 * GSTAGE);
    cudaFuncSetAttribute(gemm_gates, cudaFuncAttributeMaxDynamicSharedMemorySize,
                         3 * GSTAGE_G);

    cudaStream_t s = 0;

    // ---- graph preprocessing ----
    cudaMemsetAsync(tmp, 0, 3 * MAXN * sizeof(int), s);
    k_degree<<<ceildiv(E, 256), 256, 0, s>>>(src, dst, E);
    k_scan<<<1, 1024, 0, s>>>(N);
    k_fill<<<ceildiv(E, 256), 256, 0, s>>>(src, dst, E);

    // ---- all weight/bias preprocessing in one kernel ----
    k_prep_all<<<ceildiv(E6, 256), 256, 0, s>>>(
        l1_Wx, l2_Wx, l3_Wx, lin1_W, lin2_W,
        l1_bx, l1_bh, l1_b, l2_bx, l2_bh, l2_b, l3_bx, l3_bh, l3_b);

    // ================= layer 1 (F=3, H=256) — fully fused ===================
    k_l1a<<<ceildiv(N, 256), 256, 0, s>>>(x, xcf, N);
    k_l1gates<<<ceildiv(Npad, 64), 256, 0, s>>>(x, xcf, l1_wc + 512, bufB, N, Npad);
    // lin1: [N,256]@[256,128] + lrelu -> H2 (T0 of layer 2, fp16, zero-padded)
    gemm_mma2<<<dim3(2, Mt), 256, 3 * GSTAGE, s>>>(
        bufB, bb + O_BL1, lin1_b, H2, N, 256, 128);

    // ================= layer 2 (F=128, H=128) =================
    k_spmv<128, 0><<<ceildiv(Npad, 16), 256, 0, s>>>(H2, nullptr, T1, N, Npad);
    k_spmv<128, 1><<<ceildiv(Npad, 16), 256, 0, s>>>(T1, H2, T2, N, Npad);
    // fused gate GEMM (A = {H2, T1, T2}) + gate eval -> bufB [Npad, 128]
    gemm_gates<<<dim3(2, Mt), 256, 3 * GSTAGE_G, s>>>(
        H2, T1, T2, bb + O_B2, wb + 768, l2_wc + 256, bufB, N, 128, 128,
        nullptr, nullptr, nullptr);
    // lin2: [N,128]@[128,64] + lrelu -> H2 (T0 of layer 3, 64-wide)
    gemm_mma2<<<dim3(1, Mt), 256, 3 * GSTAGE, s>>>(
        bufB, bb + O_BL2, lin2_b, H2, N, 128, 64);

    // ================= layer 3 (F=64, H=64) =================
    k_spmv<64, 0><<<ceildiv(Npad, 32), 256, 0, s>>>(H2, nullptr, T1, N, Npad);
    k_spmv<64, 1><<<ceildiv(Npad, 32), 256, 0, s>>>(T1, H2, T2, N, Npad);
    // fused gate GEMM + gate eval + lin3 -> out directly
    gemm_gates<<<dim3(1, Mt), 256, 3 * GSTAGE_G, s>>>(
        H2, T1, T2, bb + O_B3, wb + 1152, l3_wc + 128, bufB, N, 64, 64,
        lin3_W, lin3_b, out);
}